// round 8
// baseline (speedup 1.0000x reference)
#include <cuda_runtime.h>
#include <math.h>
#include <stdint.h>

// ---------------- problem constants ----------------
#define HID   3072
#define HEADS 24
#define HD    128
#define MLP_  12288
#define L_    2304
#define TXT_  256
#define IMG   2048
#define N1    (3*HID + MLP_)      // 21504
#define K2    (HID + MLP_)        // 15360
#define QKV3  (3*HID)             // 9216
#define ADA_SPLITS 12

// ---------------- scratch ----------------
__device__ __align__(256) float g_silu[HID];
__device__ __align__(256) float g_emb[3*HID];
__device__ __align__(256) float g_adapart[ADA_SPLITS][3*HID];
__device__ __align__(256) float g_normx[(size_t)L_*HID];
__device__ __align__(256) float g_proj[(size_t)L_*QKV3];
__device__ __align__(256) float g_q[(size_t)HEADS*L_*HD];
__device__ __align__(256) float g_k[(size_t)HEADS*L_*HD];
__device__ __align__(256) float g_v[(size_t)HEADS*L_*HD];
__device__ __align__(256) float g_cat[(size_t)L_*K2];
__device__ __align__(256) float g_w1t[(size_t)HID*N1];     // lin1_w^T [N1][HID], tf32
__device__ __align__(256) float g_w2t[(size_t)K2*HID];     // lin2_w^T [HID][K2], tf32

// ---------------- tf32 / async helpers ----------------
__device__ __forceinline__ float f2tf(float x) {
    uint32_t u;
    asm("cvt.rna.tf32.f32 %0, %1;" : "=r"(u) : "f"(x));
    return __uint_as_float(u);
}
__device__ __forceinline__ void mma_tf32(float& c0, float& c1, float& c2, float& c3,
                                         uint32_t a0, uint32_t a1, uint32_t a2, uint32_t a3,
                                         uint32_t b0, uint32_t b1) {
    asm volatile("mma.sync.aligned.m16n8k8.row.col.f32.tf32.tf32.f32 "
                 "{%0,%1,%2,%3}, {%4,%5,%6,%7}, {%8,%9}, {%0,%1,%2,%3};"
                 : "+f"(c0), "+f"(c1), "+f"(c2), "+f"(c3)
                 : "r"(a0), "r"(a1), "r"(a2), "r"(a3), "r"(b0), "r"(b1));
}
__device__ __forceinline__ void cp16(float* dst, const float* src) {
    uint32_t d = (uint32_t)__cvta_generic_to_shared(dst);
    asm volatile("cp.async.cg.shared.global [%0], [%1], 16;\n" :: "r"(d), "l"(src));
}
__device__ __forceinline__ void ldmx4(uint32_t* r, const float* p) {
    uint32_t a = (uint32_t)__cvta_generic_to_shared(p);
    asm volatile("ldmatrix.sync.aligned.m8n8.x4.shared.b16 {%0,%1,%2,%3}, [%4];"
                 : "=r"(r[0]), "=r"(r[1]), "=r"(r[2]), "=r"(r[3]) : "r"(a));
}
#define CP_COMMIT() asm volatile("cp.async.commit_group;\n" ::: "memory")
#define CP_WAIT2()  asm volatile("cp.async.wait_group 2;\n" ::: "memory")

// ---------------- 0: weight transpose + tf32 round: out[N][K] = tf32(in[K][N]^T) ----
__global__ void wtrans_kernel(const float* __restrict__ in, float* __restrict__ out,
                              int K, int N) {
    __shared__ float t[32][33];
    int bn = blockIdx.x * 32, bk = blockIdx.y * 32;
    int x = threadIdx.x, y = threadIdx.y;      // 32 x 8
    #pragma unroll
    for (int i = 0; i < 32; i += 8)
        t[y + i][x] = f2tf(in[(size_t)(bk + y + i) * N + bn + x]);
    __syncthreads();
    #pragma unroll
    for (int i = 0; i < 32; i += 8)
        out[(size_t)(bn + y + i) * K + bk + x] = t[x][y + i];
}

// ---------------- 1: silu ----------------
__global__ void silu_kernel(const float* __restrict__ temb) {
    int i = blockIdx.x * 256 + threadIdx.x;
    if (i < HID) {
        float t = temb[i];
        g_silu[i] = t / (1.f + __expf(-t));
    }
}

// ---------------- 2a: adaLN GEMV split-K partials ----------------
__global__ void ada_split_kernel(const float* __restrict__ ada_w) {
    int j = blockIdx.x * 256 + threadIdx.x;
    int ks = blockIdx.y;
    int k0 = ks * (HID / ADA_SPLITS);
    float acc = 0.f;
    const float* wp = ada_w + (size_t)k0 * (3*HID) + j;
    #pragma unroll 8
    for (int i = 0; i < HID / ADA_SPLITS; i++)
        acc += g_silu[k0 + i] * wp[(size_t)i * (3*HID)];
    g_adapart[ks][j] = acc;
}

// ---------------- 2b: adaLN reduce + bias ----------------
__global__ void ada_reduce_kernel(const float* __restrict__ ada_b) {
    int j = blockIdx.x * 256 + threadIdx.x;
    if (j >= 3*HID) return;
    float acc = ada_b[j];
    #pragma unroll
    for (int s = 0; s < ADA_SPLITS; s++) acc += g_adapart[s][j];
    g_emb[j] = acc;
}

// ---------------- 3: layernorm + scale/shift (writes tf32-rounded) ----------------
__global__ void ln_kernel(const float* __restrict__ x) {
    int t = blockIdx.x;
    const float* row = x + (size_t)t * HID;
    float s = 0.f, s2 = 0.f;
    for (int i = threadIdx.x; i < HID; i += 256) {
        float v = row[i];
        s += v; s2 += v * v;
    }
    #pragma unroll
    for (int o = 16; o; o >>= 1) {
        s  += __shfl_xor_sync(~0u, s,  o);
        s2 += __shfl_xor_sync(~0u, s2, o);
    }
    __shared__ float rs[8], rs2[8], smu, srinv;
    int w = threadIdx.x >> 5, lane = threadIdx.x & 31;
    if (lane == 0) { rs[w] = s; rs2[w] = s2; }
    __syncthreads();
    if (threadIdx.x == 0) {
        float a = 0.f, b = 0.f;
        #pragma unroll
        for (int i = 0; i < 8; i++) { a += rs[i]; b += rs2[i]; }
        float mu = a / HID;
        float var = b / HID - mu * mu;
        smu = mu; srinv = rsqrtf(var + 1e-6f);
    }
    __syncthreads();
    float mu = smu, rinv = srinv;
    for (int i = threadIdx.x; i < HID; i += 256) {
        float sc = 1.f + g_emb[HID + i];
        float sh = g_emb[i];
        g_normx[(size_t)t * HID + i] = f2tf((row[i] - mu) * rinv * sc + sh);
    }
}

// ---------------- tf32 GEMM: 128x128x16 tiles, cp.async 4-stage, LDSM A and B ----
// A [M][K] row-major, B = W^T [N][K] row-major (both tf32 pre-rounded).
// Both tiles stored in smem as [row][AST]; all fragments via ldmatrix.x4.
#define AST 20
#define STAGES 4
#define A_STG (128*AST)
#define B_STG (128*AST)
#define GEMM_SMEM ((STAGES*(A_STG + B_STG)) * sizeof(float))

template<int MODE>
__global__ __launch_bounds__(256, 2) void tgemm_k(
    const float* __restrict__ A, const float* __restrict__ B,
    const float* __restrict__ bias, const float* __restrict__ resid,
    const float* __restrict__ gate,
    float* __restrict__ C, float* __restrict__ C2, int M, int N, int K)
{
    extern __shared__ float sm[];
    float* As = sm;
    float* Bs = sm + STAGES * A_STG;

    int tid = threadIdx.x;
    int wid = tid >> 5, lane = tid & 31;
    int wm = wid >> 2, wn = wid & 3;
    int bm = blockIdx.y, bn = blockIdx.x;

    const float* Ab = A + (size_t)bm * 128 * K;
    const float* Bb = B + (size_t)bn * 128 * K;   // B^T rows = n

    float acc[4][4][4];
    #pragma unroll
    for (int i = 0; i < 4; i++)
        #pragma unroll
        for (int j = 0; j < 4; j++)
            #pragma unroll
            for (int q = 0; q < 4; q++) acc[i][j][q] = 0.f;

    int nkt = K / 16;

    #define LOAD_TILE(stg, kt_) do {                                            \
        int kg = (kt_) * 16;                                                    \
        float* as_ = As + (stg) * A_STG;                                        \
        float* bs_ = Bs + (stg) * B_STG;                                        \
        _Pragma("unroll")                                                       \
        for (int i_ = 0; i_ < 2; i_++) {                                        \
            int id = tid + i_ * 256;                                            \
            int row = id >> 2, c = (id & 3) * 4;                                \
            cp16(as_ + row * AST + c, Ab + (size_t)row * K + kg + c);           \
            cp16(bs_ + row * AST + c, Bb + (size_t)row * K + kg + c);           \
        }                                                                       \
    } while (0)

    #pragma unroll
    for (int s = 0; s < STAGES - 1; s++) {
        LOAD_TILE(s, s);
        CP_COMMIT();
    }

    int lrow = lane & 15;
    int lkc  = (lane >> 4) * 4;

    for (int kt = 0; kt < nkt; kt++) {
        CP_WAIT2();
        __syncthreads();
        int s = kt & (STAGES - 1);
        if (kt + STAGES - 1 < nkt) {
            LOAD_TILE((kt + STAGES - 1) & (STAGES - 1), kt + STAGES - 1);
        }
        CP_COMMIT();

        const float* as_ = As + s * A_STG;
        const float* bs_ = Bs + s * B_STG;

        #pragma unroll
        for (int ks = 0; ks < 2; ks++) {
            uint32_t af[4][4], bg[2][4];
            #pragma unroll
            for (int mt = 0; mt < 4; mt++) {
                int m = wm * 64 + mt * 16 + lrow;
                ldmx4(af[mt], as_ + m * AST + ks * 8 + lkc);
            }
            #pragma unroll
            for (int nt2 = 0; nt2 < 2; nt2++) {
                int n = wn * 32 + nt2 * 16 + lrow;
                ldmx4(bg[nt2], bs_ + n * AST + ks * 8 + lkc);
            }
            #pragma unroll
            for (int mt = 0; mt < 4; mt++)
                #pragma unroll
                for (int nt = 0; nt < 4; nt++) {
                    // nt tile n-range: wn*32 + nt*8; bg[nt>>1]: [0]=n..+8,[1]=n+8..+16 halves
                    uint32_t b0 = (nt & 1) ? bg[nt >> 1][1] : bg[nt >> 1][0];
                    uint32_t b1 = (nt & 1) ? bg[nt >> 1][3] : bg[nt >> 1][2];
                    mma_tf32(acc[mt][nt][0], acc[mt][nt][1], acc[mt][nt][2], acc[mt][nt][3],
                             af[mt][0], af[mt][1], af[mt][2], af[mt][3], b0, b1);
                }
        }
    }
    #undef LOAD_TILE

    #pragma unroll
    for (int mt = 0; mt < 4; mt++) {
        int r0 = bm * 128 + wm * 64 + mt * 16 + (lane >> 2);
        #pragma unroll
        for (int nt = 0; nt < 4; nt++) {
            int c0 = bn * 128 + wn * 32 + nt * 8 + 2 * (lane & 3);
            float bia0 = bias[c0], bia1 = bias[c0 + 1];
            float t00 = acc[mt][nt][0] + bia0, t01 = acc[mt][nt][1] + bia1;
            float t10 = acc[mt][nt][2] + bia0, t11 = acc[mt][nt][3] + bia1;
            if (MODE == 1) {
                size_t o0 = (size_t)r0 * N + c0;
                size_t o1 = (size_t)(r0 + 8) * N + c0;
                float gg0 = gate[c0], gg1 = gate[c0 + 1];
                float2 r_0 = *(const float2*)(resid + o0);
                float2 r_1 = *(const float2*)(resid + o1);
                *(float2*)(C + o0) = make_float2(r_0.x + t00 * gg0, r_0.y + t01 * gg1);
                *(float2*)(C + o1) = make_float2(r_1.x + t10 * gg0, r_1.y + t11 * gg1);
            } else {
                if (c0 < QKV3) {
                    size_t o0 = (size_t)r0 * QKV3 + c0;
                    size_t o1 = (size_t)(r0 + 8) * QKV3 + c0;
                    *(float2*)(C + o0) = make_float2(t00, t01);
                    *(float2*)(C + o1) = make_float2(t10, t11);
                } else {
                    int cc = c0 - QKV3;
                    size_t o0 = (size_t)r0 * K2 + HID + cc;
                    size_t o1 = (size_t)(r0 + 8) * K2 + HID + cc;
                    const float kA = 0.7978845608028654f, kB = 0.044715f;
                    float g00 = 0.5f * t00 * (1.f + tanhf(kA * (t00 + kB * t00 * t00 * t00)));
                    float g01 = 0.5f * t01 * (1.f + tanhf(kA * (t01 + kB * t01 * t01 * t01)));
                    float g10 = 0.5f * t10 * (1.f + tanhf(kA * (t10 + kB * t10 * t10 * t10)));
                    float g11 = 0.5f * t11 * (1.f + tanhf(kA * (t11 + kB * t11 * t11 * t11)));
                    *(float2*)(C2 + o0) = make_float2(f2tf(g00), f2tf(g01));
                    *(float2*)(C2 + o1) = make_float2(f2tf(g10), f2tf(g11));
                }
            }
        }
    }
}

// ---------------- 5: qkv split + rmsnorm + rope ----------------
__global__ void qkv_kernel(const float* __restrict__ cosb, const float* __restrict__ sinb,
                           const float* __restrict__ qn,   const float* __restrict__ kn) {
    int t = blockIdx.x, h = blockIdx.y, d = threadIdx.x;
    const float* p = g_proj + (size_t)t * QKV3 + h * HD + d;
    float qv = p[0], kv = p[HID], vv = p[2*HID];

    float sq = qv * qv, sk = kv * kv;
    #pragma unroll
    for (int o = 16; o; o >>= 1) {
        sq += __shfl_xor_sync(~0u, sq, o);
        sk += __shfl_xor_sync(~0u, sk, o);
    }
    __shared__ float rq[4], rk[4];
    int w = d >> 5;
    if ((d & 31) == 0) { rq[w] = sq; rk[w] = sk; }
    __syncthreads();
    sq = rq[0] + rq[1] + rq[2] + rq[3];
    sk = rk[0] + rk[1] + rk[2] + rk[3];
    qv = qv * rsqrtf(sq / HD + 1e-6f) * qn[d];
    kv = kv * rsqrtf(sk / HD + 1e-6f) * kn[d];

    if (t < IMG) {
        float c = cosb[(size_t)t * HD + d];
        float s = sinb[(size_t)t * HD + d];
        float qo = __shfl_xor_sync(~0u, qv, 1);
        float ko = __shfl_xor_sync(~0u, kv, 1);
        float qr = (d & 1) ? qo : -qo;
        float kr = (d & 1) ? ko : -ko;
        qv = qv * c + qr * s;
        kv = kv * c + kr * s;
    }
    const float scale = 0.08838834764831845f;
    size_t o = ((size_t)h * L_ + t) * HD + d;
    g_q[o] = f2tf(qv * scale);
    g_k[o] = f2tf(kv);
    g_v[o] = f2tf(vv);
}

// ---------------- 7: flash attention, BQ=128, register-resident Q ----------------
#define QSTR 132
#define VSTR 136
#define PSTR 68
#define OFF_QP 0
#define OFF_KS (128*QSTR)
#define OFF_VS (OFF_KS + 64*QSTR)
#define ATTN_F (OFF_VS + 64*VSTR)
#define ATTN_SMEM (ATTN_F * sizeof(float))

__global__ __launch_bounds__(256) void attn_kernel() {
    extern __shared__ float smf[];
    float* qst = smf + OFF_QP;
    float* ks  = smf + OFF_KS;
    float* vs  = smf + OFF_VS;

    int h  = blockIdx.y;
    int q0 = blockIdx.x * 128;
    const float* Qp = g_q + ((size_t)h * L_ + q0) * HD;
    const float* Kp = g_k + (size_t)h * L_ * HD;
    const float* Vp = g_v + (size_t)h * L_ * HD;

    int tid = threadIdx.x;
    int wid = tid >> 5, lane = tid & 31;
    int r0 = wid * 16 + (lane >> 2);
    int lq = lane & 3;

    for (int i = tid; i < 128 * 32; i += 256) {
        int r = i >> 5, c4 = (i & 31) * 4;
        *(float4*)&qst[r * QSTR + c4] = *(const float4*)(Qp + (size_t)r * HD + c4);
    }
    __syncthreads();

    uint32_t qf[16][4];
    #pragma unroll
    for (int kk = 0; kk < 16; kk++) {
        int kr = kk * 8 + lq;
        qf[kk][0] = __float_as_uint(qst[r0 * QSTR + kr]);
        qf[kk][1] = __float_as_uint(qst[(r0 + 8) * QSTR + kr]);
        qf[kk][2] = __float_as_uint(qst[r0 * QSTR + kr + 4]);
        qf[kk][3] = __float_as_uint(qst[(r0 + 8) * QSTR + kr + 4]);
    }
    __syncthreads();

    float m0 = -1e30f, m1 = -1e30f, l0 = 0.f, l1 = 0.f;
    float o[16][4];
    #pragma unroll
    for (int i = 0; i < 16; i++)
        #pragma unroll
        for (int j = 0; j < 4; j++) o[i][j] = 0.f;

    for (int k0 = 0; k0 < L_; k0 += 64) {
        for (int i = tid; i < 64 * 32; i += 256) {
            int r = i >> 5, c4 = (i & 31) * 4;
            *(float4*)&ks[r * QSTR + c4] = *(const float4*)(Kp + (size_t)(k0 + r) * HD + c4);
            *(float4*)&vs[r * VSTR + c4] = *(const float4*)(Vp + (size_t)(k0 + r) * HD + c4);
        }
        __syncthreads();

        float s[8][4];
        #pragma unroll
        for (int nt = 0; nt < 8; nt++)
            #pragma unroll
            for (int j = 0; j < 4; j++) s[nt][j] = 0.f;

        #pragma unroll
        for (int kk = 0; kk < 16; kk++) {
            int kr = kk * 8 + lq;
            #pragma unroll
            for (int nt = 0; nt < 8; nt++) {
                int n0 = nt * 8 + (lane >> 2);
                uint32_t b0 = __float_as_uint(ks[n0 * QSTR + kr]);
                uint32_t b1 = __float_as_uint(ks[n0 * QSTR + kr + 4]);
                mma_tf32(s[nt][0], s[nt][1], s[nt][2], s[nt][3],
                         qf[kk][0], qf[kk][1], qf[kk][2], qf[kk][3], b0, b1);
            }
        }

        float rmax0 = -1e30f, rmax1 = -1e30f;
        #pragma unroll
        for (int nt = 0; nt < 8; nt++) {
            rmax0 = fmaxf(rmax0, fmaxf(s[nt][0], s[nt][1]));
            rmax1 = fmaxf(rmax1, fmaxf(s[nt][2], s[nt][3]));
        }
        #pragma unroll
        for (int off = 1; off <= 2; off <<= 1) {
            rmax0 = fmaxf(rmax0, __shfl_xor_sync(~0u, rmax0, off));
            rmax1 = fmaxf(rmax1, __shfl_xor_sync(~0u, rmax1, off));
        }
        float mn0 = fmaxf(m0, rmax0), mn1 = fmaxf(m1, rmax1);
        float al0 = __expf(m0 - mn0), al1 = __expf(m1 - mn1);

        float rs0 = 0.f, rs1 = 0.f;
        #pragma unroll
        for (int nt = 0; nt < 8; nt++) {
            float p0 = __expf(s[nt][0] - mn0);
            float p1 = __expf(s[nt][1] - mn0);
            float p2 = __expf(s[nt][2] - mn1);
            float p3 = __expf(s[nt][3] - mn1);
            rs0 += p0 + p1; rs1 += p2 + p3;
            int c = nt * 8 + 2 * lq;
            *(float2*)&qst[r0 * PSTR + c] = make_float2(f2tf(p0), f2tf(p1));
            *(float2*)&qst[(r0 + 8) * PSTR + c] = make_float2(f2tf(p2), f2tf(p3));
        }
        #pragma unroll
        for (int off = 1; off <= 2; off <<= 1) {
            rs0 += __shfl_xor_sync(~0u, rs0, off);
            rs1 += __shfl_xor_sync(~0u, rs1, off);
        }
        l0 = l0 * al0 + rs0;  m0 = mn0;
        l1 = l1 * al1 + rs1;  m1 = mn1;

        #pragma unroll
        for (int nt = 0; nt < 16; nt++) {
            o[nt][0] *= al0; o[nt][1] *= al0;
            o[nt][2] *= al1; o[nt][3] *= al1;
        }
        __syncwarp();

        #pragma unroll
        for (int kk = 0; kk < 8; kk++) {
            int kr = kk * 8 + lq;
            uint32_t a0 = __float_as_uint(qst[r0 * PSTR + kr]);
            uint32_t a1 = __float_as_uint(qst[(r0 + 8) * PSTR + kr]);
            uint32_t a2 = __float_as_uint(qst[r0 * PSTR + kr + 4]);
            uint32_t a3 = __float_as_uint(qst[(r0 + 8) * PSTR + kr + 4]);
            #pragma unroll
            for (int nt = 0; nt < 16; nt++) {
                int n0 = nt * 8 + (lane >> 2);
                uint32_t b0 = __float_as_uint(vs[kr * VSTR + n0]);
                uint32_t b1 = __float_as_uint(vs[(kr + 4) * VSTR + n0]);
                mma_tf32(o[nt][0], o[nt][1], o[nt][2], o[nt][3], a0, a1, a2, a3, b0, b1);
            }
        }
        __syncthreads();
    }

    float inv0 = 1.f / l0, inv1 = 1.f / l1;
    #pragma unroll
    for (int nt = 0; nt < 16; nt++) {
        int c = h * HD + nt * 8 + 2 * lq;
        size_t o0 = (size_t)(q0 + r0) * K2 + c;
        size_t o1 = (size_t)(q0 + r0 + 8) * K2 + c;
        *(float2*)&g_cat[o0] = make_float2(f2tf(o[nt][0] * inv0), f2tf(o[nt][1] * inv0));
        *(float2*)&g_cat[o1] = make_float2(f2tf(o[nt][2] * inv1), f2tf(o[nt][3] * inv1));
    }
}

// ---------------- launch ----------------
extern "C" void kernel_launch(void* const* d_in, const int* in_sizes, int n_in,
                              void* d_out, int out_size) {
    const float* hidden = (const float*)d_in[0];
    const float* temb   = (const float*)d_in[1];
    const float* cosb   = (const float*)d_in[2];
    const float* sinb   = (const float*)d_in[3];
    const float* ada_w  = (const float*)d_in[4];
    const float* ada_b  = (const float*)d_in[5];
    const float* lin1_w = (const float*)d_in[6];
    const float* lin1_b = (const float*)d_in[7];
    const float* lin2_w = (const float*)d_in[8];
    const float* lin2_b = (const float*)d_in[9];
    float* out = (float*)d_out;

    float *p_normx, *p_proj, *p_cat, *p_emb, *p_w1t, *p_w2t;
    cudaGetSymbolAddress((void**)&p_normx, g_normx);
    cudaGetSymbolAddress((void**)&p_proj,  g_proj);
    cudaGetSymbolAddress((void**)&p_cat,   g_cat);
    cudaGetSymbolAddress((void**)&p_emb,   g_emb);
    cudaGetSymbolAddress((void**)&p_w1t,   g_w1t);
    cudaGetSymbolAddress((void**)&p_w2t,   g_w2t);

    cudaFuncSetAttribute(attn_kernel,
                         cudaFuncAttributeMaxDynamicSharedMemorySize, (int)ATTN_SMEM);
    cudaFuncSetAttribute(tgemm_k<1>,
                         cudaFuncAttributeMaxDynamicSharedMemorySize, (int)GEMM_SMEM);
    cudaFuncSetAttribute(tgemm_k<2>,
                         cudaFuncAttributeMaxDynamicSharedMemorySize, (int)GEMM_SMEM);

    // transpose + tf32-round weights: W^T rows = output features
    wtrans_kernel<<<dim3(N1 / 32, HID / 32), dim3(32, 8)>>>(lin1_w, p_w1t, HID, N1);
    wtrans_kernel<<<dim3(HID / 32, K2 / 32), dim3(32, 8)>>>(lin2_w, p_w2t, K2, HID);

    silu_kernel<<<(HID + 255) / 256, 256>>>(temb);
    ada_split_kernel<<<dim3(3 * HID / 256, ADA_SPLITS), 256>>>(ada_w);
    ada_reduce_kernel<<<(3 * HID + 255) / 256, 256>>>(ada_b);
    ln_kernel<<<L_, 256>>>(hidden);

    tgemm_k<2><<<dim3(N1 / 128, L_ / 128), 256, GEMM_SMEM>>>(
        p_normx, p_w1t, lin1_b, nullptr, nullptr, p_proj, p_cat, L_, N1, HID);

    qkv_kernel<<<dim3(L_, HEADS), HD>>>(cosb, sinb,
                                        (const float*)d_in[10], (const float*)d_in[11]);
    attn_kernel<<<dim3(L_ / 128, HEADS), 256, ATTN_SMEM>>>();

    tgemm_k<1><<<dim3(HID / 128, L_ / 128), 256, GEMM_SMEM>>>(
        p_cat, p_w2t, lin2_b, hidden, p_emb + 2 * HID, out, nullptr, L_, HID, K2);
}

// round 9
// speedup vs baseline: 1.0656x; 1.0656x over previous
#include <cuda_runtime.h>
#include <math.h>
#include <stdint.h>

// ---------------- problem constants ----------------
#define HID   3072
#define HEADS 24
#define HD    128
#define MLP_  12288
#define L_    2304
#define TXT_  256
#define IMG   2048
#define N1    (3*HID + MLP_)      // 21504
#define K2    (HID + MLP_)        // 15360
#define QKV3  (3*HID)             // 9216
#define ADA_SPLITS 12

// ---------------- scratch ----------------
__device__ __align__(256) float g_silu[HID];
__device__ __align__(256) float g_emb[3*HID];
__device__ __align__(256) float g_adapart[ADA_SPLITS][3*HID];
__device__ __align__(256) float g_normx[(size_t)L_*HID];
__device__ __align__(256) float g_proj[(size_t)L_*QKV3];
__device__ __align__(256) float g_q[(size_t)HEADS*L_*HD];
__device__ __align__(256) float g_k[(size_t)HEADS*L_*HD];
__device__ __align__(256) float g_v[(size_t)HEADS*L_*HD];
__device__ __align__(256) float g_cat[(size_t)L_*K2];
__device__ __align__(256) float g_w1t[(size_t)HID*N1];     // tf32-rounded lin1_w
__device__ __align__(256) float g_w2t[(size_t)K2*HID];     // tf32-rounded lin2_w

// ---------------- tf32 / async helpers ----------------
__device__ __forceinline__ float f2tf(float x) {
    uint32_t u;
    asm("cvt.rna.tf32.f32 %0, %1;" : "=r"(u) : "f"(x));
    return __uint_as_float(u);
}
__device__ __forceinline__ void mma_tf32(float& c0, float& c1, float& c2, float& c3,
                                         uint32_t a0, uint32_t a1, uint32_t a2, uint32_t a3,
                                         uint32_t b0, uint32_t b1) {
    asm volatile("mma.sync.aligned.m16n8k8.row.col.f32.tf32.tf32.f32 "
                 "{%0,%1,%2,%3}, {%4,%5,%6,%7}, {%8,%9}, {%0,%1,%2,%3};"
                 : "+f"(c0), "+f"(c1), "+f"(c2), "+f"(c3)
                 : "r"(a0), "r"(a1), "r"(a2), "r"(a3), "r"(b0), "r"(b1));
}
__device__ __forceinline__ void cp16(float* dst, const float* src) {
    uint32_t d = (uint32_t)__cvta_generic_to_shared(dst);
    asm volatile("cp.async.cg.shared.global [%0], [%1], 16;\n" :: "r"(d), "l"(src));
}
__device__ __forceinline__ void ldmx4(uint32_t* r, const float* p) {
    uint32_t a = (uint32_t)__cvta_generic_to_shared(p);
    asm volatile("ldmatrix.sync.aligned.m8n8.x4.shared.b16 {%0,%1,%2,%3}, [%4];"
                 : "=r"(r[0]), "=r"(r[1]), "=r"(r[2]), "=r"(r[3]) : "r"(a));
}
#define CP_COMMIT() asm volatile("cp.async.commit_group;\n" ::: "memory")
#define CP_WAIT2()  asm volatile("cp.async.wait_group 2;\n" ::: "memory")
#define CP_WAIT0()  asm volatile("cp.async.wait_group 0;\n" ::: "memory")

// ---------------- 0: weight rounding (straight copy) ----------------
__global__ void wround_kernel(const float* __restrict__ w, float* __restrict__ o, int n4) {
    int i = blockIdx.x * 256 + threadIdx.x;
    if (i < n4) {
        float4 v = ((const float4*)w)[i];
        float4 t = make_float4(f2tf(v.x), f2tf(v.y), f2tf(v.z), f2tf(v.w));
        ((float4*)o)[i] = t;
    }
}

// ---------------- 1: silu ----------------
__global__ void silu_kernel(const float* __restrict__ temb) {
    int i = blockIdx.x * 256 + threadIdx.x;
    if (i < HID) {
        float t = temb[i];
        g_silu[i] = t / (1.f + __expf(-t));
    }
}

// ---------------- 2a: adaLN GEMV split-K partials ----------------
__global__ void ada_split_kernel(const float* __restrict__ ada_w) {
    int j = blockIdx.x * 256 + threadIdx.x;
    int ks = blockIdx.y;
    int k0 = ks * (HID / ADA_SPLITS);
    float acc = 0.f;
    const float* wp = ada_w + (size_t)k0 * (3*HID) + j;
    #pragma unroll 8
    for (int i = 0; i < HID / ADA_SPLITS; i++)
        acc += g_silu[k0 + i] * wp[(size_t)i * (3*HID)];
    g_adapart[ks][j] = acc;
}

// ---------------- 2b: adaLN reduce + bias ----------------
__global__ void ada_reduce_kernel(const float* __restrict__ ada_b) {
    int j = blockIdx.x * 256 + threadIdx.x;
    if (j >= 3*HID) return;
    float acc = ada_b[j];
    #pragma unroll
    for (int s = 0; s < ADA_SPLITS; s++) acc += g_adapart[s][j];
    g_emb[j] = acc;
}

// ---------------- 3: layernorm + scale/shift (writes tf32-rounded) ----------------
__global__ void ln_kernel(const float* __restrict__ x) {
    int t = blockIdx.x;
    const float* row = x + (size_t)t * HID;
    float s = 0.f, s2 = 0.f;
    for (int i = threadIdx.x; i < HID; i += 256) {
        float v = row[i];
        s += v; s2 += v * v;
    }
    #pragma unroll
    for (int o = 16; o; o >>= 1) {
        s  += __shfl_xor_sync(~0u, s,  o);
        s2 += __shfl_xor_sync(~0u, s2, o);
    }
    __shared__ float rs[8], rs2[8], smu, srinv;
    int w = threadIdx.x >> 5, lane = threadIdx.x & 31;
    if (lane == 0) { rs[w] = s; rs2[w] = s2; }
    __syncthreads();
    if (threadIdx.x == 0) {
        float a = 0.f, b = 0.f;
        #pragma unroll
        for (int i = 0; i < 8; i++) { a += rs[i]; b += rs2[i]; }
        float mu = a / HID;
        float var = b / HID - mu * mu;
        smu = mu; srinv = rsqrtf(var + 1e-6f);
    }
    __syncthreads();
    float mu = smu, rinv = srinv;
    for (int i = threadIdx.x; i < HID; i += 256) {
        float sc = 1.f + g_emb[HID + i];
        float sh = g_emb[i];
        g_normx[(size_t)t * HID + i] = f2tf((row[i] - mu) * rinv * sc + sh);
    }
}

// ---------------- tf32 GEMM (R7 layout): 128x128x16, cp.async 4-stage, LDSM A ----
#define AST 20
#define BST 136
#define STAGES 4
#define A_STG (128*AST)
#define B_STG (16*BST)
#define GEMM_SMEM ((STAGES*(A_STG + B_STG)) * sizeof(float))

template<int MODE>
__global__ __launch_bounds__(256, 2) void tgemm_k(
    const float* __restrict__ A, const float* __restrict__ B,
    const float* __restrict__ bias, const float* __restrict__ resid,
    const float* __restrict__ gate,
    float* __restrict__ C, float* __restrict__ C2, int M, int N, int K)
{
    extern __shared__ float sm[];
    float* As = sm;
    float* Bs = sm + STAGES * A_STG;

    int tid = threadIdx.x;
    int wid = tid >> 5, lane = tid & 31;
    int wm = wid >> 2, wn = wid & 3;
    int bm = blockIdx.y, bn = blockIdx.x;

    const float* Ab = A + (size_t)bm * 128 * K;
    const float* Bb = B + (size_t)bn * 128;

    float acc[4][4][4];
    #pragma unroll
    for (int i = 0; i < 4; i++)
        #pragma unroll
        for (int j = 0; j < 4; j++)
            #pragma unroll
            for (int q = 0; q < 4; q++) acc[i][j][q] = 0.f;

    int nkt = K / 16;

    #define LOAD_TILE(stg, kt_) do {                                            \
        int kg = (kt_) * 16;                                                    \
        float* as_ = As + (stg) * A_STG;                                        \
        float* bs_ = Bs + (stg) * B_STG;                                        \
        _Pragma("unroll")                                                       \
        for (int i_ = 0; i_ < 2; i_++) {                                        \
            int id = tid + i_ * 256;                                            \
            int row = id >> 2, c = (id & 3) * 4;                                \
            cp16(as_ + row * AST + c, Ab + (size_t)row * K + kg + c);           \
        }                                                                       \
        _Pragma("unroll")                                                       \
        for (int i_ = 0; i_ < 2; i_++) {                                        \
            int id = tid + i_ * 256;                                            \
            int row = id >> 5, c = (id & 31) * 4;                               \
            cp16(bs_ + row * BST + c, Bb + (size_t)(kg + row) * N + c);         \
        }                                                                       \
    } while (0)

    #pragma unroll
    for (int s = 0; s < STAGES - 1; s++) {
        LOAD_TILE(s, s);
        CP_COMMIT();
    }

    int lrow = lane & 15;
    int lkc  = (lane >> 4) * 4;

    for (int kt = 0; kt < nkt; kt++) {
        CP_WAIT2();
        __syncthreads();
        int s = kt & (STAGES - 1);
        if (kt + STAGES - 1 < nkt) {
            LOAD_TILE((kt + STAGES - 1) & (STAGES - 1), kt + STAGES - 1);
        }
        CP_COMMIT();

        const float* as_ = As + s * A_STG;
        const float* bs_ = Bs + s * B_STG;

        #pragma unroll
        for (int ks = 0; ks < 2; ks++) {
            uint32_t af[4][4], bf[4][2];
            #pragma unroll
            for (int mt = 0; mt < 4; mt++) {
                int m = wm * 64 + mt * 16 + lrow;
                ldmx4(af[mt], as_ + m * AST + ks * 8 + lkc);
            }
            int kr = ks * 8 + (lane & 3);
            #pragma unroll
            for (int nt = 0; nt < 4; nt++) {
                int n0 = wn * 32 + nt * 8 + (lane >> 2);
                bf[nt][0] = __float_as_uint(bs_[kr * BST + n0]);
                bf[nt][1] = __float_as_uint(bs_[(kr + 4) * BST + n0]);
            }
            #pragma unroll
            for (int mt = 0; mt < 4; mt++)
                #pragma unroll
                for (int nt = 0; nt < 4; nt++)
                    mma_tf32(acc[mt][nt][0], acc[mt][nt][1], acc[mt][nt][2], acc[mt][nt][3],
                             af[mt][0], af[mt][1], af[mt][2], af[mt][3],
                             bf[nt][0], bf[nt][1]);
        }
    }
    #undef LOAD_TILE

    #pragma unroll
    for (int mt = 0; mt < 4; mt++) {
        int r0 = bm * 128 + wm * 64 + mt * 16 + (lane >> 2);
        #pragma unroll
        for (int nt = 0; nt < 4; nt++) {
            int c0 = bn * 128 + wn * 32 + nt * 8 + 2 * (lane & 3);
            float bia0 = bias[c0], bia1 = bias[c0 + 1];
            float t00 = acc[mt][nt][0] + bia0, t01 = acc[mt][nt][1] + bia1;
            float t10 = acc[mt][nt][2] + bia0, t11 = acc[mt][nt][3] + bia1;
            if (MODE == 1) {
                size_t o0 = (size_t)r0 * N + c0;
                size_t o1 = (size_t)(r0 + 8) * N + c0;
                float gg0 = gate[c0], gg1 = gate[c0 + 1];
                float2 r_0 = *(const float2*)(resid + o0);
                float2 r_1 = *(const float2*)(resid + o1);
                *(float2*)(C + o0) = make_float2(r_0.x + t00 * gg0, r_0.y + t01 * gg1);
                *(float2*)(C + o1) = make_float2(r_1.x + t10 * gg0, r_1.y + t11 * gg1);
            } else {
                if (c0 < QKV3) {
                    size_t o0 = (size_t)r0 * QKV3 + c0;
                    size_t o1 = (size_t)(r0 + 8) * QKV3 + c0;
                    *(float2*)(C + o0) = make_float2(t00, t01);
                    *(float2*)(C + o1) = make_float2(t10, t11);
                } else {
                    int cc = c0 - QKV3;
                    size_t o0 = (size_t)r0 * K2 + HID + cc;
                    size_t o1 = (size_t)(r0 + 8) * K2 + HID + cc;
                    const float kA = 0.7978845608028654f, kB = 0.044715f;
                    float g00 = 0.5f * t00 * (1.f + tanhf(kA * (t00 + kB * t00 * t00 * t00)));
                    float g01 = 0.5f * t01 * (1.f + tanhf(kA * (t01 + kB * t01 * t01 * t01)));
                    float g10 = 0.5f * t10 * (1.f + tanhf(kA * (t10 + kB * t10 * t10 * t10)));
                    float g11 = 0.5f * t11 * (1.f + tanhf(kA * (t11 + kB * t11 * t11 * t11)));
                    *(float2*)(C2 + o0) = make_float2(f2tf(g00), f2tf(g01));
                    *(float2*)(C2 + o1) = make_float2(f2tf(g10), f2tf(g11));
                }
            }
        }
    }
}

// ---------------- 5: qkv split + rmsnorm + rope ----------------
__global__ void qkv_kernel(const float* __restrict__ cosb, const float* __restrict__ sinb,
                           const float* __restrict__ qn,   const float* __restrict__ kn) {
    int t = blockIdx.x, h = blockIdx.y, d = threadIdx.x;
    const float* p = g_proj + (size_t)t * QKV3 + h * HD + d;
    float qv = p[0], kv = p[HID], vv = p[2*HID];

    float sq = qv * qv, sk = kv * kv;
    #pragma unroll
    for (int o = 16; o; o >>= 1) {
        sq += __shfl_xor_sync(~0u, sq, o);
        sk += __shfl_xor_sync(~0u, sk, o);
    }
    __shared__ float rq[4], rk[4];
    int w = d >> 5;
    if ((d & 31) == 0) { rq[w] = sq; rk[w] = sk; }
    __syncthreads();
    sq = rq[0] + rq[1] + rq[2] + rq[3];
    sk = rk[0] + rk[1] + rk[2] + rk[3];
    qv = qv * rsqrtf(sq / HD + 1e-6f) * qn[d];
    kv = kv * rsqrtf(sk / HD + 1e-6f) * kn[d];

    if (t < IMG) {
        float c = cosb[(size_t)t * HD + d];
        float s = sinb[(size_t)t * HD + d];
        float qo = __shfl_xor_sync(~0u, qv, 1);
        float ko = __shfl_xor_sync(~0u, kv, 1);
        float qr = (d & 1) ? qo : -qo;
        float kr = (d & 1) ? ko : -ko;
        qv = qv * c + qr * s;
        kv = kv * c + kr * s;
    }
    const float scale = 0.08838834764831845f;
    size_t o = ((size_t)h * L_ + t) * HD + d;
    g_q[o] = f2tf(qv * scale);
    g_k[o] = f2tf(kv);
    g_v[o] = f2tf(vv);
}

// ---------------- 7: flash attention, BQ=128, reg-Q, double-buffered cp.async K/V --
#define QSTR 132
#define VSTR 136
#define PSTR 68
#define KBUF (64*QSTR)
#define VBUF (64*VSTR)
#define OFF_QP 0
#define OFF_KS (128*QSTR)
#define OFF_VS (OFF_KS + 2*KBUF)
#define ATTN_F (OFF_VS + 2*VBUF)
#define ATTN_SMEM (ATTN_F * sizeof(float))
#define NCHUNK (L_ / 64)

__global__ __launch_bounds__(256) void attn_kernel() {
    extern __shared__ float smf[];
    float* qst = smf + OFF_QP;   // q stage, later P
    float* ksb = smf + OFF_KS;   // 2 x K buffers
    float* vsb = smf + OFF_VS;   // 2 x V buffers

    int h  = blockIdx.y;
    int q0 = blockIdx.x * 128;
    const float* Qp = g_q + ((size_t)h * L_ + q0) * HD;
    const float* Kp = g_k + (size_t)h * L_ * HD;
    const float* Vp = g_v + (size_t)h * L_ * HD;

    int tid = threadIdx.x;
    int wid = tid >> 5, lane = tid & 31;
    int r0 = wid * 16 + (lane >> 2);
    int lq = lane & 3;

    // chunk loader: each thread 16 cp16 (8 K + 8 V)
    int lr = tid >> 3, lc = (tid & 7) * 16;   // 32 rows per pass, 128 cols in 16B units
    #define LOAD_CHUNK(ci, buf) do {                                             \
        float* kd = ksb + (buf) * KBUF;                                          \
        float* vd = vsb + (buf) * VBUF;                                          \
        const float* kg_ = Kp + (size_t)(ci) * 64 * HD;                          \
        const float* vg_ = Vp + (size_t)(ci) * 64 * HD;                          \
        _Pragma("unroll")                                                        \
        for (int ii = 0; ii < 2; ii++) {                                         \
            int r = lr + ii * 32;                                                \
            cp16(kd + r * QSTR + lc,      kg_ + (size_t)r * HD + lc);            \
            cp16(kd + r * QSTR + lc + 4,  kg_ + (size_t)r * HD + lc + 4);        \
            cp16(kd + r * QSTR + lc + 8,  kg_ + (size_t)r * HD + lc + 8);        \
            cp16(kd + r * QSTR + lc + 12, kg_ + (size_t)r * HD + lc + 12);       \
            cp16(vd + r * VSTR + lc,      vg_ + (size_t)r * HD + lc);            \
            cp16(vd + r * VSTR + lc + 4,  vg_ + (size_t)r * HD + lc + 4);        \
            cp16(vd + r * VSTR + lc + 8,  vg_ + (size_t)r * HD + lc + 8);        \
            cp16(vd + r * VSTR + lc + 12, vg_ + (size_t)r * HD + lc + 12);       \
        }                                                                        \
    } while (0)

    // stage Q into smem, extract fragments
    for (int i = tid; i < 128 * 32; i += 256) {
        int r = i >> 5, c4 = (i & 31) * 4;
        *(float4*)&qst[r * QSTR + c4] = *(const float4*)(Qp + (size_t)r * HD + c4);
    }
    // prologue: chunk 0 into buf 0 (overlaps with Q extraction)
    LOAD_CHUNK(0, 0);
    CP_COMMIT();
    __syncthreads();

    uint32_t qf[16][4];
    #pragma unroll
    for (int kk = 0; kk < 16; kk++) {
        int kr = kk * 8 + lq;
        qf[kk][0] = __float_as_uint(qst[r0 * QSTR + kr]);
        qf[kk][1] = __float_as_uint(qst[(r0 + 8) * QSTR + kr]);
        qf[kk][2] = __float_as_uint(qst[r0 * QSTR + kr + 4]);
        qf[kk][3] = __float_as_uint(qst[(r0 + 8) * QSTR + kr + 4]);
    }

    float m0 = -1e30f, m1 = -1e30f, l0 = 0.f, l1 = 0.f;
    float o[16][4];
    #pragma unroll
    for (int i = 0; i < 16; i++)
        #pragma unroll
        for (int j = 0; j < 4; j++) o[i][j] = 0.f;

    for (int ci = 0; ci < NCHUNK; ci++) {
        int buf = ci & 1;
        CP_WAIT0();
        __syncthreads();                    // chunk ci visible; all warps done with buf^1
        if (ci + 1 < NCHUNK) {
            LOAD_CHUNK(ci + 1, buf ^ 1);    // overlaps compute below
            CP_COMMIT();
        }
        const float* ks = ksb + buf * KBUF;
        const float* vs = vsb + buf * VBUF;

        // S = Q @ K^T : 16 q-rows x 64 k-cols per warp
        float s[8][4];
        #pragma unroll
        for (int nt = 0; nt < 8; nt++)
            #pragma unroll
            for (int j = 0; j < 4; j++) s[nt][j] = 0.f;

        #pragma unroll
        for (int kk = 0; kk < 16; kk++) {
            int kr = kk * 8 + lq;
            #pragma unroll
            for (int nt = 0; nt < 8; nt++) {
                int n0 = nt * 8 + (lane >> 2);
                uint32_t b0 = __float_as_uint(ks[n0 * QSTR + kr]);
                uint32_t b1 = __float_as_uint(ks[n0 * QSTR + kr + 4]);
                mma_tf32(s[nt][0], s[nt][1], s[nt][2], s[nt][3],
                         qf[kk][0], qf[kk][1], qf[kk][2], qf[kk][3], b0, b1);
            }
        }

        // in-warp online softmax
        float rmax0 = -1e30f, rmax1 = -1e30f;
        #pragma unroll
        for (int nt = 0; nt < 8; nt++) {
            rmax0 = fmaxf(rmax0, fmaxf(s[nt][0], s[nt][1]));
            rmax1 = fmaxf(rmax1, fmaxf(s[nt][2], s[nt][3]));
        }
        #pragma unroll
        for (int off = 1; off <= 2; off <<= 1) {
            rmax0 = fmaxf(rmax0, __shfl_xor_sync(~0u, rmax0, off));
            rmax1 = fmaxf(rmax1, __shfl_xor_sync(~0u, rmax1, off));
        }
        float mn0 = fmaxf(m0, rmax0), mn1 = fmaxf(m1, rmax1);
        float al0 = __expf(m0 - mn0), al1 = __expf(m1 - mn1);

        float rs0 = 0.f, rs1 = 0.f;
        #pragma unroll
        for (int nt = 0; nt < 8; nt++) {
            float p0 = __expf(s[nt][0] - mn0);
            float p1 = __expf(s[nt][1] - mn0);
            float p2 = __expf(s[nt][2] - mn1);
            float p3 = __expf(s[nt][3] - mn1);
            rs0 += p0 + p1; rs1 += p2 + p3;
            int c = nt * 8 + 2 * lq;
            *(float2*)&qst[r0 * PSTR + c] = make_float2(f2tf(p0), f2tf(p1));
            *(float2*)&qst[(r0 + 8) * PSTR + c] = make_float2(f2tf(p2), f2tf(p3));
        }
        #pragma unroll
        for (int off = 1; off <= 2; off <<= 1) {
            rs0 += __shfl_xor_sync(~0u, rs0, off);
            rs1 += __shfl_xor_sync(~0u, rs1, off);
        }
        l0 = l0 * al0 + rs0;  m0 = mn0;
        l1 = l1 * al1 + rs1;  m1 = mn1;

        #pragma unroll
        for (int nt = 0; nt < 16; nt++) {
            o[nt][0] *= al0; o[nt][1] *= al0;
            o[nt][2] *= al1; o[nt][3] *= al1;
        }
        __syncwarp();

        // O += P @ V
        #pragma unroll
        for (int kk = 0; kk < 8; kk++) {
            int kr = kk * 8 + lq;
            uint32_t a0 = __float_as_uint(qst[r0 * PSTR + kr]);
            uint32_t a1 = __float_as_uint(qst[(r0 + 8) * PSTR + kr]);
            uint32_t a2 = __float_as_uint(qst[r0 * PSTR + kr + 4]);
            uint32_t a3 = __float_as_uint(qst[(r0 + 8) * PSTR + kr + 4]);
            #pragma unroll
            for (int nt = 0; nt < 16; nt++) {
                int n0 = nt * 8 + (lane >> 2);
                uint32_t b0 = __float_as_uint(vs[kr * VSTR + n0]);
                uint32_t b1 = __float_as_uint(vs[(kr + 4) * VSTR + n0]);
                mma_tf32(o[nt][0], o[nt][1], o[nt][2], o[nt][3], a0, a1, a2, a3, b0, b1);
            }
        }
    }
    #undef LOAD_CHUNK

    float inv0 = 1.f / l0, inv1 = 1.f / l1;
    #pragma unroll
    for (int nt = 0; nt < 16; nt++) {
        int c = h * HD + nt * 8 + 2 * lq;
        size_t o0 = (size_t)(q0 + r0) * K2 + c;
        size_t o1 = (size_t)(q0 + r0 + 8) * K2 + c;
        *(float2*)&g_cat[o0] = make_float2(f2tf(o[nt][0] * inv0), f2tf(o[nt][1] * inv0));
        *(float2*)&g_cat[o1] = make_float2(f2tf(o[nt][2] * inv1), f2tf(o[nt][3] * inv1));
    }
}

// ---------------- launch ----------------
extern "C" void kernel_launch(void* const* d_in, const int* in_sizes, int n_in,
                              void* d_out, int out_size) {
    const float* hidden = (const float*)d_in[0];
    const float* temb   = (const float*)d_in[1];
    const float* cosb   = (const float*)d_in[2];
    const float* sinb   = (const float*)d_in[3];
    const float* ada_w  = (const float*)d_in[4];
    const float* ada_b  = (const float*)d_in[5];
    const float* lin1_w = (const float*)d_in[6];
    const float* lin1_b = (const float*)d_in[7];
    const float* lin2_w = (const float*)d_in[8];
    const float* lin2_b = (const float*)d_in[9];
    float* out = (float*)d_out;

    float *p_normx, *p_proj, *p_cat, *p_emb, *p_w1t, *p_w2t;
    cudaGetSymbolAddress((void**)&p_normx, g_normx);
    cudaGetSymbolAddress((void**)&p_proj,  g_proj);
    cudaGetSymbolAddress((void**)&p_cat,   g_cat);
    cudaGetSymbolAddress((void**)&p_emb,   g_emb);
    cudaGetSymbolAddress((void**)&p_w1t,   g_w1t);
    cudaGetSymbolAddress((void**)&p_w2t,   g_w2t);

    cudaFuncSetAttribute(attn_kernel,
                         cudaFuncAttributeMaxDynamicSharedMemorySize, (int)ATTN_SMEM);
    cudaFuncSetAttribute(tgemm_k<1>,
                         cudaFuncAttributeMaxDynamicSharedMemorySize, (int)GEMM_SMEM);
    cudaFuncSetAttribute(tgemm_k<2>,
                         cudaFuncAttributeMaxDynamicSharedMemorySize, (int)GEMM_SMEM);

    {
        int n4a = (int)((size_t)HID * N1 / 4);
        int n4b = (int)((size_t)K2 * HID / 4);
        wround_kernel<<<(n4a + 255) / 256, 256>>>(lin1_w, p_w1t, n4a);
        wround_kernel<<<(n4b + 255) / 256, 256>>>(lin2_w, p_w2t, n4b);
    }

    silu_kernel<<<(HID + 255) / 256, 256>>>(temb);
    ada_split_kernel<<<dim3(3 * HID / 256, ADA_SPLITS), 256>>>(ada_w);
    ada_reduce_kernel<<<(3 * HID + 255) / 256, 256>>>(ada_b);
    ln_kernel<<<L_, 256>>>(hidden);

    tgemm_k<2><<<dim3(N1 / 128, L_ / 128), 256, GEMM_SMEM>>>(
        p_normx, p_w1t, lin1_b, nullptr, nullptr, p_proj, p_cat, L_, N1, HID);

    qkv_kernel<<<dim3(L_, HEADS), HD>>>(cosb, sinb,
                                        (const float*)d_in[10], (const float*)d_in[11]);
    attn_kernel<<<dim3(L_ / 128, HEADS), 256, ATTN_SMEM>>>();

    tgemm_k<1><<<dim3(HID / 128, L_ / 128), 256, GEMM_SMEM>>>(
        p_cat, p_w2t, lin2_b, hidden, p_emb + 2 * HID, out, nullptr, L_, HID, K2);
}

// round 12
// speedup vs baseline: 1.1360x; 1.0660x over previous
#include <cuda_runtime.h>
#include <math.h>
#include <stdint.h>

// ---------------- problem constants ----------------
#define HID   3072
#define HEADS 24
#define HD    128
#define MLP_  12288
#define L_    2304
#define TXT_  256
#define IMG   2048
#define N1    (3*HID + MLP_)      // 21504
#define K2    (HID + MLP_)        // 15360
#define QKV3  (3*HID)             // 9216
#define ADA_SPLITS 12

// ---------------- scratch ----------------
__device__ __align__(256) float g_silu[HID];
__device__ __align__(256) float g_emb[3*HID];
__device__ __align__(256) float g_adapart[ADA_SPLITS][3*HID];
__device__ __align__(256) float g_normx[(size_t)L_*HID];
__device__ __align__(256) float g_proj[(size_t)L_*QKV3];
__device__ __align__(256) float g_q[(size_t)HEADS*L_*HD];
__device__ __align__(256) float g_k[(size_t)HEADS*L_*HD];
__device__ __align__(256) float g_v[(size_t)HEADS*L_*HD];
__device__ __align__(256) float g_cat[(size_t)L_*K2];
__device__ __align__(256) float g_w1t[(size_t)HID*N1];     // tf32-rounded lin1_w
__device__ __align__(256) float g_w2t[(size_t)K2*HID];     // tf32-rounded lin2_w

// ---------------- tf32 / async helpers ----------------
__device__ __forceinline__ float f2tf(float x) {
    uint32_t u;
    asm("cvt.rna.tf32.f32 %0, %1;" : "=r"(u) : "f"(x));
    return __uint_as_float(u);
}
__device__ __forceinline__ void mma_tf32(float& c0, float& c1, float& c2, float& c3,
                                         uint32_t a0, uint32_t a1, uint32_t a2, uint32_t a3,
                                         uint32_t b0, uint32_t b1) {
    asm volatile("mma.sync.aligned.m16n8k8.row.col.f32.tf32.tf32.f32 "
                 "{%0,%1,%2,%3}, {%4,%5,%6,%7}, {%8,%9}, {%0,%1,%2,%3};"
                 : "+f"(c0), "+f"(c1), "+f"(c2), "+f"(c3)
                 : "r"(a0), "r"(a1), "r"(a2), "r"(a3), "r"(b0), "r"(b1));
}
__device__ __forceinline__ void cp16(float* dst, const float* src) {
    uint32_t d = (uint32_t)__cvta_generic_to_shared(dst);
    asm volatile("cp.async.cg.shared.global [%0], [%1], 16;\n" :: "r"(d), "l"(src));
}
__device__ __forceinline__ void ldmx4(uint32_t* r, const float* p) {
    uint32_t a = (uint32_t)__cvta_generic_to_shared(p);
    asm volatile("ldmatrix.sync.aligned.m8n8.x4.shared.b16 {%0,%1,%2,%3}, [%4];"
                 : "=r"(r[0]), "=r"(r[1]), "=r"(r[2]), "=r"(r[3]) : "r"(a));
}
#define CP_COMMIT() asm volatile("cp.async.commit_group;\n" ::: "memory")
#define CP_WAIT0()  asm volatile("cp.async.wait_group 0;\n" ::: "memory")

// ---------------- 0: weight rounding ----------------
__global__ void wround_kernel(const float* __restrict__ w, float* __restrict__ o, int n4) {
    int i = blockIdx.x * 256 + threadIdx.x;
    if (i < n4) {
        float4 v = ((const float4*)w)[i];
        float4 t = make_float4(f2tf(v.x), f2tf(v.y), f2tf(v.z), f2tf(v.w));
        ((float4*)o)[i] = t;
    }
}

// ---------------- 1: silu ----------------
__global__ void silu_kernel(const float* __restrict__ temb) {
    int i = blockIdx.x * 256 + threadIdx.x;
    if (i < HID) {
        float t = temb[i];
        g_silu[i] = t / (1.f + __expf(-t));
    }
}

// ---------------- 2a/2b: adaLN GEMV split-K ----------------
__global__ void ada_split_kernel(const float* __restrict__ ada_w) {
    int j = blockIdx.x * 256 + threadIdx.x;
    int ks = blockIdx.y;
    int k0 = ks * (HID / ADA_SPLITS);
    float acc = 0.f;
    const float* wp = ada_w + (size_t)k0 * (3*HID) + j;
    #pragma unroll 8
    for (int i = 0; i < HID / ADA_SPLITS; i++)
        acc += g_silu[k0 + i] * wp[(size_t)i * (3*HID)];
    g_adapart[ks][j] = acc;
}
__global__ void ada_reduce_kernel(const float* __restrict__ ada_b) {
    int j = blockIdx.x * 256 + threadIdx.x;
    if (j >= 3*HID) return;
    float acc = ada_b[j];
    #pragma unroll
    for (int s = 0; s < ADA_SPLITS; s++) acc += g_adapart[s][j];
    g_emb[j] = acc;
}

// ---------------- 3: layernorm + scale/shift (writes tf32-rounded) ----------------
__global__ void ln_kernel(const float* __restrict__ x) {
    int t = blockIdx.x;
    const float* row = x + (size_t)t * HID;
    float s = 0.f, s2 = 0.f;
    for (int i = threadIdx.x; i < HID; i += 256) {
        float v = row[i];
        s += v; s2 += v * v;
    }
    #pragma unroll
    for (int o = 16; o; o >>= 1) {
        s  += __shfl_xor_sync(~0u, s,  o);
        s2 += __shfl_xor_sync(~0u, s2, o);
    }
    __shared__ float rs[8], rs2[8], smu, srinv;
    int w = threadIdx.x >> 5, lane = threadIdx.x & 31;
    if (lane == 0) { rs[w] = s; rs2[w] = s2; }
    __syncthreads();
    if (threadIdx.x == 0) {
        float a = 0.f, b = 0.f;
        #pragma unroll
        for (int i = 0; i < 8; i++) { a += rs[i]; b += rs2[i]; }
        float mu = a / HID;
        float var = b / HID - mu * mu;
        smu = mu; srinv = rsqrtf(var + 1e-6f);
    }
    __syncthreads();
    float mu = smu, rinv = srinv;
    for (int i = threadIdx.x; i < HID; i += 256) {
        float sc = 1.f + g_emb[HID + i];
        float sh = g_emb[i];
        g_normx[(size_t)t * HID + i] = f2tf((row[i] - mu) * rinv * sc + sh);
    }
}

// ---------------- tf32 GEMM: 128x128 tile, k-depth 32, 2-stage double buffer ------
// 256 threads / 8 warps (2x4 grid), warp tile 64x32, ldmatrix A, scalar B.
// MODE 1: C = resid + (acc + bias) * gate
// MODE 2: split: n < QKV3 -> C (stride QKV3); else gelu -> C2 (stride K2, +HID)
#define AST 36          // 32 k floats + 4 pad; 144B rows, LDSM conflict-free
#define BST 136
#define A_STG (128*AST)
#define B_STG (32*BST)
#define GEMM_SMEM ((2*(A_STG + B_STG)) * sizeof(float))

template<int MODE>
__global__ __launch_bounds__(256, 2) void tgemm_k(
    const float* __restrict__ A, const float* __restrict__ B,
    const float* __restrict__ bias, const float* __restrict__ resid,
    const float* __restrict__ gate,
    float* __restrict__ C, float* __restrict__ C2, int M, int N, int K)
{
    extern __shared__ float sm[];
    float* As = sm;                       // [2][128][AST]
    float* Bs = sm + 2 * A_STG;           // [2][32][BST]

    int tid = threadIdx.x;
    int wid = tid >> 5, lane = tid & 31;
    int wm = wid >> 2, wn = wid & 3;
    int bm = blockIdx.y, bn = blockIdx.x;

    const float* Ab = A + (size_t)bm * 128 * K;
    const float* Bb = B + (size_t)bn * 128;

    float acc[4][4][4];
    #pragma unroll
    for (int i = 0; i < 4; i++)
        #pragma unroll
        for (int j = 0; j < 4; j++)
            #pragma unroll
            for (int q = 0; q < 4; q++) acc[i][j][q] = 0.f;

    int nkt = K / 32;

    // per stage: A 128 rows x 32 floats (8x16B/row) = 1024 cp16; B 32 rows x 128 = 1024
    #define LOAD_TILE(stg, kt_) do {                                            \
        int kg = (kt_) * 32;                                                    \
        float* as_ = As + (stg) * A_STG;                                        \
        float* bs_ = Bs + (stg) * B_STG;                                        \
        _Pragma("unroll")                                                       \
        for (int i_ = 0; i_ < 4; i_++) {                                        \
            int id = tid + i_ * 256;                                            \
            int row = id >> 3, c = (id & 7) * 4;                                \
            cp16(as_ + row * AST + c, Ab + (size_t)row * K + kg + c);           \
        }                                                                       \
        _Pragma("unroll")                                                       \
        for (int i_ = 0; i_ < 4; i_++) {                                        \
            int id = tid + i_ * 256;                                            \
            int row = id >> 5, c = (id & 31) * 4;                               \
            cp16(bs_ + row * BST + c, Bb + (size_t)(kg + row) * N + c);         \
        }                                                                       \
    } while (0)

    LOAD_TILE(0, 0);
    CP_COMMIT();

    int lrow = lane & 15;
    int lkc  = (lane >> 4) * 4;

    for (int kt = 0; kt < nkt; kt++) {
        int buf = kt & 1;
        CP_WAIT0();
        __syncthreads();                 // stage kt visible; buf^1 free everywhere
        if (kt + 1 < nkt) {
            LOAD_TILE(buf ^ 1, kt + 1);  // overlaps compute below
            CP_COMMIT();
        }

        const float* as_ = As + buf * A_STG;
        const float* bs_ = Bs + buf * B_STG;

        #pragma unroll
        for (int ks = 0; ks < 4; ks++) {
            uint32_t af[4][4], bf[4][2];
            #pragma unroll
            for (int mt = 0; mt < 4; mt++) {
                int m = wm * 64 + mt * 16 + lrow;
                ldmx4(af[mt], as_ + m * AST + ks * 8 + lkc);
            }
            int kr = ks * 8 + (lane & 3);
            #pragma unroll
            for (int nt = 0; nt < 4; nt++) {
                int n0 = wn * 32 + nt * 8 + (lane >> 2);
                bf[nt][0] = __float_as_uint(bs_[kr * BST + n0]);
                bf[nt][1] = __float_as_uint(bs_[(kr + 4) * BST + n0]);
            }
            #pragma unroll
            for (int mt = 0; mt < 4; mt++)
                #pragma unroll
                for (int nt = 0; nt < 4; nt++)
                    mma_tf32(acc[mt][nt][0], acc[mt][nt][1], acc[mt][nt][2], acc[mt][nt][3],
                             af[mt][0], af[mt][1], af[mt][2], af[mt][3],
                             bf[nt][0], bf[nt][1]);
        }
    }
    #undef LOAD_TILE

    #pragma unroll
    for (int mt = 0; mt < 4; mt++) {
        int r0 = bm * 128 + wm * 64 + mt * 16 + (lane >> 2);
        #pragma unroll
        for (int nt = 0; nt < 4; nt++) {
            int c0 = bn * 128 + wn * 32 + nt * 8 + 2 * (lane & 3);
            float bia0 = bias[c0], bia1 = bias[c0 + 1];
            float t00 = acc[mt][nt][0] + bia0, t01 = acc[mt][nt][1] + bia1;
            float t10 = acc[mt][nt][2] + bia0, t11 = acc[mt][nt][3] + bia1;
            if (MODE == 1) {
                size_t o0 = (size_t)r0 * N + c0;
                size_t o1 = (size_t)(r0 + 8) * N + c0;
                float gg0 = gate[c0], gg1 = gate[c0 + 1];
                float2 r_0 = *(const float2*)(resid + o0);
                float2 r_1 = *(const float2*)(resid + o1);
                *(float2*)(C + o0) = make_float2(r_0.x + t00 * gg0, r_0.y + t01 * gg1);
                *(float2*)(C + o1) = make_float2(r_1.x + t10 * gg0, r_1.y + t11 * gg1);
            } else {
                if (c0 < QKV3) {
                    size_t o0 = (size_t)r0 * QKV3 + c0;
                    size_t o1 = (size_t)(r0 + 8) * QKV3 + c0;
                    *(float2*)(C + o0) = make_float2(t00, t01);
                    *(float2*)(C + o1) = make_float2(t10, t11);
                } else {
                    int cc = c0 - QKV3;
                    size_t o0 = (size_t)r0 * K2 + HID + cc;
                    size_t o1 = (size_t)(r0 + 8) * K2 + HID + cc;
                    const float kA = 0.7978845608028654f, kB = 0.044715f;
                    float g00 = 0.5f * t00 * (1.f + tanhf(kA * (t00 + kB * t00 * t00 * t00)));
                    float g01 = 0.5f * t01 * (1.f + tanhf(kA * (t01 + kB * t01 * t01 * t01)));
                    float g10 = 0.5f * t10 * (1.f + tanhf(kA * (t10 + kB * t10 * t10 * t10)));
                    float g11 = 0.5f * t11 * (1.f + tanhf(kA * (t11 + kB * t11 * t11 * t11)));
                    *(float2*)(C2 + o0) = make_float2(f2tf(g00), f2tf(g01));
                    *(float2*)(C2 + o1) = make_float2(f2tf(g10), f2tf(g11));
                }
            }
        }
    }
}

// ---------------- 5: qkv split + rmsnorm + rope ----------------
__global__ void qkv_kernel(const float* __restrict__ cosb, const float* __restrict__ sinb,
                           const float* __restrict__ qn,   const float* __restrict__ kn) {
    int t = blockIdx.x, h = blockIdx.y, d = threadIdx.x;
    const float* p = g_proj + (size_t)t * QKV3 + h * HD + d;
    float qv = p[0], kv = p[HID], vv = p[2*HID];

    float sq = qv * qv, sk = kv * kv;
    #pragma unroll
    for (int o = 16; o; o >>= 1) {
        sq += __shfl_xor_sync(~0u, sq, o);
        sk += __shfl_xor_sync(~0u, sk, o);
    }
    __shared__ float rq[4], rk[4];
    int w = d >> 5;
    if ((d & 31) == 0) { rq[w] = sq; rk[w] = sk; }
    __syncthreads();
    sq = rq[0] + rq[1] + rq[2] + rq[3];
    sk = rk[0] + rk[1] + rk[2] + rk[3];
    qv = qv * rsqrtf(sq / HD + 1e-6f) * qn[d];
    kv = kv * rsqrtf(sk / HD + 1e-6f) * kn[d];

    if (t < IMG) {
        float c = cosb[(size_t)t * HD + d];
        float s = sinb[(size_t)t * HD + d];
        float qo = __shfl_xor_sync(~0u, qv, 1);
        float ko = __shfl_xor_sync(~0u, kv, 1);
        float qr = (d & 1) ? qo : -qo;
        float kr = (d & 1) ? ko : -ko;
        qv = qv * c + qr * s;
        kv = kv * c + kr * s;
    }
    const float scale = 0.08838834764831845f;
    size_t o = ((size_t)h * L_ + t) * HD + d;
    g_q[o] = f2tf(qv * scale);
    g_k[o] = f2tf(kv);
    g_v[o] = f2tf(vv);
}

// ---------------- 7: flash attention, BQ=128, register-resident Q (R7 version) ----
#define QSTR 132
#define VSTR 136
#define PSTR 68
#define OFF_QP 0
#define OFF_KS (128*QSTR)
#define OFF_VS (OFF_KS + 64*QSTR)
#define ATTN_F (OFF_VS + 64*VSTR)
#define ATTN_SMEM (ATTN_F * sizeof(float))

__global__ __launch_bounds__(256) void attn_kernel() {
    extern __shared__ float smf[];
    float* qst = smf + OFF_QP;
    float* ks  = smf + OFF_KS;
    float* vs  = smf + OFF_VS;

    int h  = blockIdx.y;
    int q0 = blockIdx.x * 128;
    const float* Qp = g_q + ((size_t)h * L_ + q0) * HD;
    const float* Kp = g_k + (size_t)h * L_ * HD;
    const float* Vp = g_v + (size_t)h * L_ * HD;

    int tid = threadIdx.x;
    int wid = tid >> 5, lane = tid & 31;
    int r0 = wid * 16 + (lane >> 2);
    int lq = lane & 3;

    for (int i = tid; i < 128 * 32; i += 256) {
        int r = i >> 5, c4 = (i & 31) * 4;
        *(float4*)&qst[r * QSTR + c4] = *(const float4*)(Qp + (size_t)r * HD + c4);
    }
    __syncthreads();

    uint32_t qf[16][4];
    #pragma unroll
    for (int kk = 0; kk < 16; kk++) {
        int kr = kk * 8 + lq;
        qf[kk][0] = __float_as_uint(qst[r0 * QSTR + kr]);
        qf[kk][1] = __float_as_uint(qst[(r0 + 8) * QSTR + kr]);
        qf[kk][2] = __float_as_uint(qst[r0 * QSTR + kr + 4]);
        qf[kk][3] = __float_as_uint(qst[(r0 + 8) * QSTR + kr + 4]);
    }
    __syncthreads();

    float m0 = -1e30f, m1 = -1e30f, l0 = 0.f, l1 = 0.f;
    float o[16][4];
    #pragma unroll
    for (int i = 0; i < 16; i++)
        #pragma unroll
        for (int j = 0; j < 4; j++) o[i][j] = 0.f;

    for (int k0 = 0; k0 < L_; k0 += 64) {
        for (int i = tid; i < 64 * 32; i += 256) {
            int r = i >> 5, c4 = (i & 31) * 4;
            *(float4*)&ks[r * QSTR + c4] = *(const float4*)(Kp + (size_t)(k0 + r) * HD + c4);
            *(float4*)&vs[r * VSTR + c4] = *(const float4*)(Vp + (size_t)(k0 + r) * HD + c4);
        }
        __syncthreads();

        float s[8][4];
        #pragma unroll
        for (int nt = 0; nt < 8; nt++)
            #pragma unroll
            for (int j = 0; j < 4; j++) s[nt][j] = 0.f;

        #pragma unroll
        for (int kk = 0; kk < 16; kk++) {
            int kr = kk * 8 + lq;
            #pragma unroll
            for (int nt = 0; nt < 8; nt++) {
                int n0 = nt * 8 + (lane >> 2);
                uint32_t b0 = __float_as_uint(ks[n0 * QSTR + kr]);
                uint32_t b1 = __float_as_uint(ks[n0 * QSTR + kr + 4]);
                mma_tf32(s[nt][0], s[nt][1], s[nt][2], s[nt][3],
                         qf[kk][0], qf[kk][1], qf[kk][2], qf[kk][3], b0, b1);
            }
        }

        float rmax0 = -1e30f, rmax1 = -1e30f;
        #pragma unroll
        for (int nt = 0; nt < 8; nt++) {
            rmax0 = fmaxf(rmax0, fmaxf(s[nt][0], s[nt][1]));
            rmax1 = fmaxf(rmax1, fmaxf(s[nt][2], s[nt][3]));
        }
        #pragma unroll
        for (int off = 1; off <= 2; off <<= 1) {
            rmax0 = fmaxf(rmax0, __shfl_xor_sync(~0u, rmax0, off));
            rmax1 = fmaxf(rmax1, __shfl_xor_sync(~0u, rmax1, off));
        }
        float mn0 = fmaxf(m0, rmax0), mn1 = fmaxf(m1, rmax1);
        float al0 = __expf(m0 - mn0), al1 = __expf(m1 - mn1);

        float rs0 = 0.f, rs1 = 0.f;
        #pragma unroll
        for (int nt = 0; nt < 8; nt++) {
            float p0 = __expf(s[nt][0] - mn0);
            float p1 = __expf(s[nt][1] - mn0);
            float p2 = __expf(s[nt][2] - mn1);
            float p3 = __expf(s[nt][3] - mn1);
            rs0 += p0 + p1; rs1 += p2 + p3;
            int c = nt * 8 + 2 * lq;
            *(float2*)&qst[r0 * PSTR + c] = make_float2(f2tf(p0), f2tf(p1));
            *(float2*)&qst[(r0 + 8) * PSTR + c] = make_float2(f2tf(p2), f2tf(p3));
        }
        #pragma unroll
        for (int off = 1; off <= 2; off <<= 1) {
            rs0 += __shfl_xor_sync(~0u, rs0, off);
            rs1 += __shfl_xor_sync(~0u, rs1, off);
        }
        l0 = l0 * al0 + rs0;  m0 = mn0;
        l1 = l1 * al1 + rs1;  m1 = mn1;

        #pragma unroll
        for (int nt = 0; nt < 16; nt++) {
            o[nt][0] *= al0; o[nt][1] *= al0;
            o[nt][2] *= al1; o[nt][3] *= al1;
        }
        __syncwarp();

        #pragma unroll
        for (int kk = 0; kk < 8; kk++) {
            int kr = kk * 8 + lq;
            uint32_t a0 = __float_as_uint(qst[r0 * PSTR + kr]);
            uint32_t a1 = __float_as_uint(qst[(r0 + 8) * PSTR + kr]);
            uint32_t a2 = __float_as_uint(qst[r0 * PSTR + kr + 4]);
            uint32_t a3 = __float_as_uint(qst[(r0 + 8) * PSTR + kr + 4]);
            #pragma unroll
            for (int nt = 0; nt < 16; nt++) {
                int n0 = nt * 8 + (lane >> 2);
                uint32_t b0 = __float_as_uint(vs[kr * VSTR + n0]);
                uint32_t b1 = __float_as_uint(vs[(kr + 4) * VSTR + n0]);
                mma_tf32(o[nt][0], o[nt][1], o[nt][2], o[nt][3], a0, a1, a2, a3, b0, b1);
            }
        }
        __syncthreads();
    }

    float inv0 = 1.f / l0, inv1 = 1.f / l1;
    #pragma unroll
    for (int nt = 0; nt < 16; nt++) {
        int c = h * HD + nt * 8 + 2 * lq;
        size_t o0 = (size_t)(q0 + r0) * K2 + c;
        size_t o1 = (size_t)(q0 + r0 + 8) * K2 + c;
        *(float2*)&g_cat[o0] = make_float2(f2tf(o[nt][0] * inv0), f2tf(o[nt][1] * inv0));
        *(float2*)&g_cat[o1] = make_float2(f2tf(o[nt][2] * inv1), f2tf(o[nt][3] * inv1));
    }
}

// ---------------- launch ----------------
extern "C" void kernel_launch(void* const* d_in, const int* in_sizes, int n_in,
                              void* d_out, int out_size) {
    const float* hidden = (const float*)d_in[0];
    const float* temb   = (const float*)d_in[1];
    const float* cosb   = (const float*)d_in[2];
    const float* sinb   = (const float*)d_in[3];
    const float* ada_w  = (const float*)d_in[4];
    const float* ada_b  = (const float*)d_in[5];
    const float* lin1_w = (const float*)d_in[6];
    const float* lin1_b = (const float*)d_in[7];
    const float* lin2_w = (const float*)d_in[8];
    const float* lin2_b = (const float*)d_in[9];
    float* out = (float*)d_out;

    float *p_normx, *p_proj, *p_cat, *p_emb, *p_w1t, *p_w2t;
    cudaGetSymbolAddress((void**)&p_normx, g_normx);
    cudaGetSymbolAddress((void**)&p_proj,  g_proj);
    cudaGetSymbolAddress((void**)&p_cat,   g_cat);
    cudaGetSymbolAddress((void**)&p_emb,   g_emb);
    cudaGetSymbolAddress((void**)&p_w1t,   g_w1t);
    cudaGetSymbolAddress((void**)&p_w2t,   g_w2t);

    cudaFuncSetAttribute(attn_kernel,
                         cudaFuncAttributeMaxDynamicSharedMemorySize, (int)ATTN_SMEM);
    cudaFuncSetAttribute(tgemm_k<1>,
                         cudaFuncAttributeMaxDynamicSharedMemorySize, (int)GEMM_SMEM);
    cudaFuncSetAttribute(tgemm_k<2>,
                         cudaFuncAttributeMaxDynamicSharedMemorySize, (int)GEMM_SMEM);

    {
        int n4a = (int)((size_t)HID * N1 / 4);
        int n4b = (int)((size_t)K2 * HID / 4);
        wround_kernel<<<(n4a + 255) / 256, 256>>>(lin1_w, p_w1t, n4a);
        wround_kernel<<<(n4b + 255) / 256, 256>>>(lin2_w, p_w2t, n4b);
    }

    silu_kernel<<<(HID + 255) / 256, 256>>>(temb);
    ada_split_kernel<<<dim3(3 * HID / 256, ADA_SPLITS), 256>>>(ada_w);
    ada_reduce_kernel<<<(3 * HID + 255) / 256, 256>>>(ada_b);
    ln_kernel<<<L_, 256>>>(hidden);

    tgemm_k<2><<<dim3(N1 / 128, L_ / 128), 256, GEMM_SMEM>>>(
        p_normx, p_w1t, lin1_b, nullptr, nullptr, p_proj, p_cat, L_, N1, HID);

    qkv_kernel<<<dim3(L_, HEADS), HD>>>(cosb, sinb,
                                        (const float*)d_in[10], (const float*)d_in[11]);
    attn_kernel<<<dim3(L_ / 128, HEADS), 256, ATTN_SMEM>>>();

    tgemm_k<1><<<dim3(HID / 128, L_ / 128), 256, GEMM_SMEM>>>(
        p_cat, p_w2t, lin2_b, hidden, p_emb + 2 * HID, out, nullptr, L_, HID, K2);
}

// round 13
// speedup vs baseline: 1.1889x; 1.0466x over previous
#include <cuda_runtime.h>
#include <math.h>
#include <stdint.h>

// ---------------- problem constants ----------------
#define HID   3072
#define HEADS 24
#define HD    128
#define MLP_  12288
#define L_    2304
#define TXT_  256
#define IMG   2048
#define N1    (3*HID + MLP_)      // 21504
#define K2    (HID + MLP_)        // 15360
#define QKV3  (3*HID)             // 9216
#define ADA_SPLITS 12

// ---------------- scratch ----------------
__device__ __align__(256) float g_silu[HID];
__device__ __align__(256) float g_emb[3*HID];
__device__ __align__(256) float g_adapart[ADA_SPLITS][3*HID];
__device__ __align__(256) float g_normx[(size_t)L_*HID];
__device__ __align__(256) float g_proj[(size_t)L_*QKV3];
__device__ __align__(256) float g_q[(size_t)HEADS*L_*HD];
__device__ __align__(256) float g_k[(size_t)HEADS*L_*HD];
__device__ __align__(256) float g_v[(size_t)HEADS*L_*HD];
__device__ __align__(256) float g_cat[(size_t)L_*K2];
__device__ __align__(256) float g_w1t[(size_t)HID*N1];     // tf32-rounded lin1_w
__device__ __align__(256) float g_w2t[(size_t)K2*HID];     // tf32-rounded lin2_w

// ---------------- tf32 / async helpers ----------------
__device__ __forceinline__ float f2tf(float x) {
    uint32_t u;
    asm("cvt.rna.tf32.f32 %0, %1;" : "=r"(u) : "f"(x));
    return __uint_as_float(u);
}
__device__ __forceinline__ void mma_tf32(float& c0, float& c1, float& c2, float& c3,
                                         uint32_t a0, uint32_t a1, uint32_t a2, uint32_t a3,
                                         uint32_t b0, uint32_t b1) {
    asm volatile("mma.sync.aligned.m16n8k8.row.col.f32.tf32.tf32.f32 "
                 "{%0,%1,%2,%3}, {%4,%5,%6,%7}, {%8,%9}, {%0,%1,%2,%3};"
                 : "+f"(c0), "+f"(c1), "+f"(c2), "+f"(c3)
                 : "r"(a0), "r"(a1), "r"(a2), "r"(a3), "r"(b0), "r"(b1));
}
__device__ __forceinline__ void cp16(float* dst, const float* src) {
    uint32_t d = (uint32_t)__cvta_generic_to_shared(dst);
    asm volatile("cp.async.cg.shared.global [%0], [%1], 16;\n" :: "r"(d), "l"(src));
}
__device__ __forceinline__ void ldmx4(uint32_t* r, const float* p) {
    uint32_t a = (uint32_t)__cvta_generic_to_shared(p);
    asm volatile("ldmatrix.sync.aligned.m8n8.x4.shared.b16 {%0,%1,%2,%3}, [%4];"
                 : "=r"(r[0]), "=r"(r[1]), "=r"(r[2]), "=r"(r[3]) : "r"(a));
}
#define CP_COMMIT() asm volatile("cp.async.commit_group;\n" ::: "memory")
#define CP_WAIT0()  asm volatile("cp.async.wait_group 0;\n" ::: "memory")

// ---------------- 0: weight rounding ----------------
__global__ void wround_kernel(const float* __restrict__ w, float* __restrict__ o, int n4) {
    int i = blockIdx.x * 256 + threadIdx.x;
    if (i < n4) {
        float4 v = ((const float4*)w)[i];
        float4 t = make_float4(f2tf(v.x), f2tf(v.y), f2tf(v.z), f2tf(v.w));
        ((float4*)o)[i] = t;
    }
}

// ---------------- 1: silu ----------------
__global__ void silu_kernel(const float* __restrict__ temb) {
    int i = blockIdx.x * 256 + threadIdx.x;
    if (i < HID) {
        float t = temb[i];
        g_silu[i] = t / (1.f + __expf(-t));
    }
}

// ---------------- 2a/2b: adaLN GEMV split-K ----------------
__global__ void ada_split_kernel(const float* __restrict__ ada_w) {
    int j = blockIdx.x * 256 + threadIdx.x;
    int ks = blockIdx.y;
    int k0 = ks * (HID / ADA_SPLITS);
    float acc = 0.f;
    const float* wp = ada_w + (size_t)k0 * (3*HID) + j;
    #pragma unroll 8
    for (int i = 0; i < HID / ADA_SPLITS; i++)
        acc += g_silu[k0 + i] * wp[(size_t)i * (3*HID)];
    g_adapart[ks][j] = acc;
}
__global__ void ada_reduce_kernel(const float* __restrict__ ada_b) {
    int j = blockIdx.x * 256 + threadIdx.x;
    if (j >= 3*HID) return;
    float acc = ada_b[j];
    #pragma unroll
    for (int s = 0; s < ADA_SPLITS; s++) acc += g_adapart[s][j];
    g_emb[j] = acc;
}

// ---------------- 3: layernorm + scale/shift (writes tf32-rounded) ----------------
__global__ void ln_kernel(const float* __restrict__ x) {
    int t = blockIdx.x;
    const float* row = x + (size_t)t * HID;
    float s = 0.f, s2 = 0.f;
    for (int i = threadIdx.x; i < HID; i += 256) {
        float v = row[i];
        s += v; s2 += v * v;
    }
    #pragma unroll
    for (int o = 16; o; o >>= 1) {
        s  += __shfl_xor_sync(~0u, s,  o);
        s2 += __shfl_xor_sync(~0u, s2, o);
    }
    __shared__ float rs[8], rs2[8], smu, srinv;
    int w = threadIdx.x >> 5, lane = threadIdx.x & 31;
    if (lane == 0) { rs[w] = s; rs2[w] = s2; }
    __syncthreads();
    if (threadIdx.x == 0) {
        float a = 0.f, b = 0.f;
        #pragma unroll
        for (int i = 0; i < 8; i++) { a += rs[i]; b += rs2[i]; }
        float mu = a / HID;
        float var = b / HID - mu * mu;
        smu = mu; srinv = rsqrtf(var + 1e-6f);
    }
    __syncthreads();
    float mu = smu, rinv = srinv;
    for (int i = threadIdx.x; i < HID; i += 256) {
        float sc = 1.f + g_emb[HID + i];
        float sh = g_emb[i];
        g_normx[(size_t)t * HID + i] = f2tf((row[i] - mu) * rinv * sc + sh);
    }
}

// ---------------- tf32 GEMM: 128x128 tile, k-depth 32, 2-stage double buffer ------
// Grid: blockIdx.x = bm (fast axis -> waves cover all M-tiles, B strips L2-reused),
//       blockIdx.y = bn.
// MODE 1: C = resid + (acc + bias) * gate
// MODE 2: split: n < QKV3 -> C (stride QKV3); else gelu -> C2 (stride K2, +HID)
#define AST 36
#define BST 136
#define A_STG (128*AST)
#define B_STG (32*BST)
#define GEMM_SMEM ((2*(A_STG + B_STG)) * sizeof(float))

template<int MODE>
__global__ __launch_bounds__(256, 2) void tgemm_k(
    const float* __restrict__ A, const float* __restrict__ B,
    const float* __restrict__ bias, const float* __restrict__ resid,
    const float* __restrict__ gate,
    float* __restrict__ C, float* __restrict__ C2, int M, int N, int K)
{
    extern __shared__ float sm[];
    float* As = sm;                       // [2][128][AST]
    float* Bs = sm + 2 * A_STG;           // [2][32][BST]

    int tid = threadIdx.x;
    int wid = tid >> 5, lane = tid & 31;
    int wm = wid >> 2, wn = wid & 3;
    int bm = blockIdx.x, bn = blockIdx.y;   // bm fast -> B-strip reuse across wave

    const float* Ab = A + (size_t)bm * 128 * K;
    const float* Bb = B + (size_t)bn * 128;

    float acc[4][4][4];
    #pragma unroll
    for (int i = 0; i < 4; i++)
        #pragma unroll
        for (int j = 0; j < 4; j++)
            #pragma unroll
            for (int q = 0; q < 4; q++) acc[i][j][q] = 0.f;

    int nkt = K / 32;

    #define LOAD_TILE(stg, kt_) do {                                            \
        int kg = (kt_) * 32;                                                    \
        float* as_ = As + (stg) * A_STG;                                        \
        float* bs_ = Bs + (stg) * B_STG;                                        \
        _Pragma("unroll")                                                       \
        for (int i_ = 0; i_ < 4; i_++) {                                        \
            int id = tid + i_ * 256;                                            \
            int row = id >> 3, c = (id & 7) * 4;                                \
            cp16(as_ + row * AST + c, Ab + (size_t)row * K + kg + c);           \
        }                                                                       \
        _Pragma("unroll")                                                       \
        for (int i_ = 0; i_ < 4; i_++) {                                        \
            int id = tid + i_ * 256;                                            \
            int row = id >> 5, c = (id & 31) * 4;                               \
            cp16(bs_ + row * BST + c, Bb + (size_t)(kg + row) * N + c);         \
        }                                                                       \
    } while (0)

    LOAD_TILE(0, 0);
    CP_COMMIT();

    int lrow = lane & 15;
    int lkc  = (lane >> 4) * 4;

    for (int kt = 0; kt < nkt; kt++) {
        int buf = kt & 1;
        CP_WAIT0();
        __syncthreads();
        if (kt + 1 < nkt) {
            LOAD_TILE(buf ^ 1, kt + 1);
            CP_COMMIT();
        }

        const float* as_ = As + buf * A_STG;
        const float* bs_ = Bs + buf * B_STG;

        #pragma unroll
        for (int ks = 0; ks < 4; ks++) {
            uint32_t af[4][4], bf[4][2];
            #pragma unroll
            for (int mt = 0; mt < 4; mt++) {
                int m = wm * 64 + mt * 16 + lrow;
                ldmx4(af[mt], as_ + m * AST + ks * 8 + lkc);
            }
            int kr = ks * 8 + (lane & 3);
            #pragma unroll
            for (int nt = 0; nt < 4; nt++) {
                int n0 = wn * 32 + nt * 8 + (lane >> 2);
                bf[nt][0] = __float_as_uint(bs_[kr * BST + n0]);
                bf[nt][1] = __float_as_uint(bs_[(kr + 4) * BST + n0]);
            }
            #pragma unroll
            for (int mt = 0; mt < 4; mt++)
                #pragma unroll
                for (int nt = 0; nt < 4; nt++)
                    mma_tf32(acc[mt][nt][0], acc[mt][nt][1], acc[mt][nt][2], acc[mt][nt][3],
                             af[mt][0], af[mt][1], af[mt][2], af[mt][3],
                             bf[nt][0], bf[nt][1]);
        }
    }
    #undef LOAD_TILE

    #pragma unroll
    for (int mt = 0; mt < 4; mt++) {
        int r0 = bm * 128 + wm * 64 + mt * 16 + (lane >> 2);
        #pragma unroll
        for (int nt = 0; nt < 4; nt++) {
            int c0 = bn * 128 + wn * 32 + nt * 8 + 2 * (lane & 3);
            float bia0 = bias[c0], bia1 = bias[c0 + 1];
            float t00 = acc[mt][nt][0] + bia0, t01 = acc[mt][nt][1] + bia1;
            float t10 = acc[mt][nt][2] + bia0, t11 = acc[mt][nt][3] + bia1;
            if (MODE == 1) {
                size_t o0 = (size_t)r0 * N + c0;
                size_t o1 = (size_t)(r0 + 8) * N + c0;
                float gg0 = gate[c0], gg1 = gate[c0 + 1];
                float2 r_0 = *(const float2*)(resid + o0);
                float2 r_1 = *(const float2*)(resid + o1);
                *(float2*)(C + o0) = make_float2(r_0.x + t00 * gg0, r_0.y + t01 * gg1);
                *(float2*)(C + o1) = make_float2(r_1.x + t10 * gg0, r_1.y + t11 * gg1);
            } else {
                if (c0 < QKV3) {
                    size_t o0 = (size_t)r0 * QKV3 + c0;
                    size_t o1 = (size_t)(r0 + 8) * QKV3 + c0;
                    *(float2*)(C + o0) = make_float2(t00, t01);
                    *(float2*)(C + o1) = make_float2(t10, t11);
                } else {
                    int cc = c0 - QKV3;
                    size_t o0 = (size_t)r0 * K2 + HID + cc;
                    size_t o1 = (size_t)(r0 + 8) * K2 + HID + cc;
                    const float kA = 0.7978845608028654f, kB = 0.044715f;
                    float g00 = 0.5f * t00 * (1.f + tanhf(kA * (t00 + kB * t00 * t00 * t00)));
                    float g01 = 0.5f * t01 * (1.f + tanhf(kA * (t01 + kB * t01 * t01 * t01)));
                    float g10 = 0.5f * t10 * (1.f + tanhf(kA * (t10 + kB * t10 * t10 * t10)));
                    float g11 = 0.5f * t11 * (1.f + tanhf(kA * (t11 + kB * t11 * t11 * t11)));
                    *(float2*)(C2 + o0) = make_float2(f2tf(g00), f2tf(g01));
                    *(float2*)(C2 + o1) = make_float2(f2tf(g10), f2tf(g11));
                }
            }
        }
    }
}

// ---------------- 5: qkv split + rmsnorm + rope ----------------
__global__ void qkv_kernel(const float* __restrict__ cosb, const float* __restrict__ sinb,
                           const float* __restrict__ qn,   const float* __restrict__ kn) {
    int t = blockIdx.x, h = blockIdx.y, d = threadIdx.x;
    const float* p = g_proj + (size_t)t * QKV3 + h * HD + d;
    float qv = p[0], kv = p[HID], vv = p[2*HID];

    float sq = qv * qv, sk = kv * kv;
    #pragma unroll
    for (int o = 16; o; o >>= 1) {
        sq += __shfl_xor_sync(~0u, sq, o);
        sk += __shfl_xor_sync(~0u, sk, o);
    }
    __shared__ float rq[4], rk[4];
    int w = d >> 5;
    if ((d & 31) == 0) { rq[w] = sq; rk[w] = sk; }
    __syncthreads();
    sq = rq[0] + rq[1] + rq[2] + rq[3];
    sk = rk[0] + rk[1] + rk[2] + rk[3];
    qv = qv * rsqrtf(sq / HD + 1e-6f) * qn[d];
    kv = kv * rsqrtf(sk / HD + 1e-6f) * kn[d];

    if (t < IMG) {
        float c = cosb[(size_t)t * HD + d];
        float s = sinb[(size_t)t * HD + d];
        float qo = __shfl_xor_sync(~0u, qv, 1);
        float ko = __shfl_xor_sync(~0u, kv, 1);
        float qr = (d & 1) ? qo : -qo;
        float kr = (d & 1) ? ko : -ko;
        qv = qv * c + qr * s;
        kv = kv * c + kr * s;
    }
    const float scale = 0.08838834764831845f;
    size_t o = ((size_t)h * L_ + t) * HD + d;
    g_q[o] = f2tf(qv * scale);
    g_k[o] = f2tf(kv);
    g_v[o] = f2tf(vv);
}

// ---------------- 7: flash attention, BQ=128, register-resident Q ----------------
#define QSTR 132
#define VSTR 136
#define PSTR 68
#define OFF_QP 0
#define OFF_KS (128*QSTR)
#define OFF_VS (OFF_KS + 64*QSTR)
#define ATTN_F (OFF_VS + 64*VSTR)
#define ATTN_SMEM (ATTN_F * sizeof(float))

__global__ __launch_bounds__(256) void attn_kernel() {
    extern __shared__ float smf[];
    float* qst = smf + OFF_QP;
    float* ks  = smf + OFF_KS;
    float* vs  = smf + OFF_VS;

    int h  = blockIdx.y;
    int q0 = blockIdx.x * 128;
    const float* Qp = g_q + ((size_t)h * L_ + q0) * HD;
    const float* Kp = g_k + (size_t)h * L_ * HD;
    const float* Vp = g_v + (size_t)h * L_ * HD;

    int tid = threadIdx.x;
    int wid = tid >> 5, lane = tid & 31;
    int r0 = wid * 16 + (lane >> 2);
    int lq = lane & 3;

    for (int i = tid; i < 128 * 32; i += 256) {
        int r = i >> 5, c4 = (i & 31) * 4;
        *(float4*)&qst[r * QSTR + c4] = *(const float4*)(Qp + (size_t)r * HD + c4);
    }
    __syncthreads();

    uint32_t qf[16][4];
    #pragma unroll
    for (int kk = 0; kk < 16; kk++) {
        int kr = kk * 8 + lq;
        qf[kk][0] = __float_as_uint(qst[r0 * QSTR + kr]);
        qf[kk][1] = __float_as_uint(qst[(r0 + 8) * QSTR + kr]);
        qf[kk][2] = __float_as_uint(qst[r0 * QSTR + kr + 4]);
        qf[kk][3] = __float_as_uint(qst[(r0 + 8) * QSTR + kr + 4]);
    }
    __syncthreads();

    float m0 = -1e30f, m1 = -1e30f, l0 = 0.f, l1 = 0.f;
    float o[16][4];
    #pragma unroll
    for (int i = 0; i < 16; i++)
        #pragma unroll
        for (int j = 0; j < 4; j++) o[i][j] = 0.f;

    for (int k0 = 0; k0 < L_; k0 += 64) {
        for (int i = tid; i < 64 * 32; i += 256) {
            int r = i >> 5, c4 = (i & 31) * 4;
            *(float4*)&ks[r * QSTR + c4] = *(const float4*)(Kp + (size_t)(k0 + r) * HD + c4);
            *(float4*)&vs[r * VSTR + c4] = *(const float4*)(Vp + (size_t)(k0 + r) * HD + c4);
        }
        __syncthreads();

        float s[8][4];
        #pragma unroll
        for (int nt = 0; nt < 8; nt++)
            #pragma unroll
            for (int j = 0; j < 4; j++) s[nt][j] = 0.f;

        #pragma unroll
        for (int kk = 0; kk < 16; kk++) {
            int kr = kk * 8 + lq;
            #pragma unroll
            for (int nt = 0; nt < 8; nt++) {
                int n0 = nt * 8 + (lane >> 2);
                uint32_t b0 = __float_as_uint(ks[n0 * QSTR + kr]);
                uint32_t b1 = __float_as_uint(ks[n0 * QSTR + kr + 4]);
                mma_tf32(s[nt][0], s[nt][1], s[nt][2], s[nt][3],
                         qf[kk][0], qf[kk][1], qf[kk][2], qf[kk][3], b0, b1);
            }
        }

        float rmax0 = -1e30f, rmax1 = -1e30f;
        #pragma unroll
        for (int nt = 0; nt < 8; nt++) {
            rmax0 = fmaxf(rmax0, fmaxf(s[nt][0], s[nt][1]));
            rmax1 = fmaxf(rmax1, fmaxf(s[nt][2], s[nt][3]));
        }
        #pragma unroll
        for (int off = 1; off <= 2; off <<= 1) {
            rmax0 = fmaxf(rmax0, __shfl_xor_sync(~0u, rmax0, off));
            rmax1 = fmaxf(rmax1, __shfl_xor_sync(~0u, rmax1, off));
        }
        float mn0 = fmaxf(m0, rmax0), mn1 = fmaxf(m1, rmax1);
        float al0 = __expf(m0 - mn0), al1 = __expf(m1 - mn1);

        float rs0 = 0.f, rs1 = 0.f;
        #pragma unroll
        for (int nt = 0; nt < 8; nt++) {
            float p0 = __expf(s[nt][0] - mn0);
            float p1 = __expf(s[nt][1] - mn0);
            float p2 = __expf(s[nt][2] - mn1);
            float p3 = __expf(s[nt][3] - mn1);
            rs0 += p0 + p1; rs1 += p2 + p3;
            int c = nt * 8 + 2 * lq;
            *(float2*)&qst[r0 * PSTR + c] = make_float2(f2tf(p0), f2tf(p1));
            *(float2*)&qst[(r0 + 8) * PSTR + c] = make_float2(f2tf(p2), f2tf(p3));
        }
        #pragma unroll
        for (int off = 1; off <= 2; off <<= 1) {
            rs0 += __shfl_xor_sync(~0u, rs0, off);
            rs1 += __shfl_xor_sync(~0u, rs1, off);
        }
        l0 = l0 * al0 + rs0;  m0 = mn0;
        l1 = l1 * al1 + rs1;  m1 = mn1;

        #pragma unroll
        for (int nt = 0; nt < 16; nt++) {
            o[nt][0] *= al0; o[nt][1] *= al0;
            o[nt][2] *= al1; o[nt][3] *= al1;
        }
        __syncwarp();

        #pragma unroll
        for (int kk = 0; kk < 8; kk++) {
            int kr = kk * 8 + lq;
            uint32_t a0 = __float_as_uint(qst[r0 * PSTR + kr]);
            uint32_t a1 = __float_as_uint(qst[(r0 + 8) * PSTR + kr]);
            uint32_t a2 = __float_as_uint(qst[r0 * PSTR + kr + 4]);
            uint32_t a3 = __float_as_uint(qst[(r0 + 8) * PSTR + kr + 4]);
            #pragma unroll
            for (int nt = 0; nt < 16; nt++) {
                int n0 = nt * 8 + (lane >> 2);
                uint32_t b0 = __float_as_uint(vs[kr * VSTR + n0]);
                uint32_t b1 = __float_as_uint(vs[(kr + 4) * VSTR + n0]);
                mma_tf32(o[nt][0], o[nt][1], o[nt][2], o[nt][3], a0, a1, a2, a3, b0, b1);
            }
        }
        __syncthreads();
    }

    float inv0 = 1.f / l0, inv1 = 1.f / l1;
    #pragma unroll
    for (int nt = 0; nt < 16; nt++) {
        int c = h * HD + nt * 8 + 2 * lq;
        size_t o0 = (size_t)(q0 + r0) * K2 + c;
        size_t o1 = (size_t)(q0 + r0 + 8) * K2 + c;
        *(float2*)&g_cat[o0] = make_float2(f2tf(o[nt][0] * inv0), f2tf(o[nt][1] * inv0));
        *(float2*)&g_cat[o1] = make_float2(f2tf(o[nt][2] * inv1), f2tf(o[nt][3] * inv1));
    }
}

// ---------------- launch ----------------
extern "C" void kernel_launch(void* const* d_in, const int* in_sizes, int n_in,
                              void* d_out, int out_size) {
    const float* hidden = (const float*)d_in[0];
    const float* temb   = (const float*)d_in[1];
    const float* cosb   = (const float*)d_in[2];
    const float* sinb   = (const float*)d_in[3];
    const float* ada_w  = (const float*)d_in[4];
    const float* ada_b  = (const float*)d_in[5];
    const float* lin1_w = (const float*)d_in[6];
    const float* lin1_b = (const float*)d_in[7];
    const float* lin2_w = (const float*)d_in[8];
    const float* lin2_b = (const float*)d_in[9];
    float* out = (float*)d_out;

    float *p_normx, *p_proj, *p_cat, *p_emb, *p_w1t, *p_w2t;
    cudaGetSymbolAddress((void**)&p_normx, g_normx);
    cudaGetSymbolAddress((void**)&p_proj,  g_proj);
    cudaGetSymbolAddress((void**)&p_cat,   g_cat);
    cudaGetSymbolAddress((void**)&p_emb,   g_emb);
    cudaGetSymbolAddress((void**)&p_w1t,   g_w1t);
    cudaGetSymbolAddress((void**)&p_w2t,   g_w2t);

    cudaFuncSetAttribute(attn_kernel,
                         cudaFuncAttributeMaxDynamicSharedMemorySize, (int)ATTN_SMEM);
    cudaFuncSetAttribute(tgemm_k<1>,
                         cudaFuncAttributeMaxDynamicSharedMemorySize, (int)GEMM_SMEM);
    cudaFuncSetAttribute(tgemm_k<2>,
                         cudaFuncAttributeMaxDynamicSharedMemorySize, (int)GEMM_SMEM);

    {
        int n4a = (int)((size_t)HID * N1 / 4);
        int n4b = (int)((size_t)K2 * HID / 4);
        wround_kernel<<<(n4a + 255) / 256, 256>>>(lin1_w, p_w1t, n4a);
        wround_kernel<<<(n4b + 255) / 256, 256>>>(lin2_w, p_w2t, n4b);
    }

    silu_kernel<<<(HID + 255) / 256, 256>>>(temb);
    ada_split_kernel<<<dim3(3 * HID / 256, ADA_SPLITS), 256>>>(ada_w);
    ada_reduce_kernel<<<(3 * HID + 255) / 256, 256>>>(ada_b);
    ln_kernel<<<L_, 256>>>(hidden);

    // grids: bm on x (fast) so concurrent waves share B strips in L2
    tgemm_k<2><<<dim3(L_ / 128, N1 / 128), 256, GEMM_SMEM>>>(
        p_normx, p_w1t, lin1_b, nullptr, nullptr, p_proj, p_cat, L_, N1, HID);

    qkv_kernel<<<dim3(L_, HEADS), HD>>>(cosb, sinb,
                                        (const float*)d_in[10], (const float*)d_in[11]);
    attn_kernel<<<dim3(L_ / 128, HEADS), 256, ATTN_SMEM>>>();

    tgemm_k<1><<<dim3(L_ / 128, HID / 128), 256, GEMM_SMEM>>>(
        p_cat, p_w2t, lin2_b, hidden, p_emb + 2 * HID, out, nullptr, L_, HID, K2);
}